// round 12
// baseline (speedup 1.0000x reference)
#include <cuda_runtime.h>
#include <cuda_fp16.h>
#include <cstdint>

// ============================================================================
// StockMixer GB300 — R12: R11 + phase-2 consolidation (kB2 folded into kC1,
// halved kC2 partial traffic) and kA barrier trims.
// ============================================================================

#define PWA 72
#define X_OFF  0
#define HT_OFF 18432
#define SCR_BASE 27648
#define SMEM_SZ ((27648 + 1856) * 4)    // 118016 B (x2 blocks <= 228K)

#define NTH 256

// -------------------- device globals --------------------
__device__ __align__(16) uint2 g_Wf[7][4096];
__device__ __align__(16) uint4 g_Lf[6][2048];
__device__ float g_h[4096 * 224];
__device__ float g_bpart[4096];
__device__ float g_cpart[128 * 64 * 224];       // 7.3 MB partials
__device__ float g_gw[64];

// -------------------- helpers --------------------
__device__ __forceinline__ float hswf(float v) {
    return v * fminf(fmaxf(v + 3.0f, 0.0f), 6.0f) * (1.0f / 6.0f);
}

__device__ __forceinline__ int wslotA(int k) {
    int q = (k >> 1) & 7;
    int pos = ((q & 3) << 1) | (q >> 2);
    return ((k >> 4) << 3) + pos;
}
__device__ __forceinline__ int swz(int r) { return ((r >> 2) & 3) << 3; }

__device__ __forceinline__ void mma16816(float* d, uint32_t a0, uint32_t a1,
                                         uint32_t a2, uint32_t a3,
                                         uint32_t b0, uint32_t b1) {
    asm volatile(
        "mma.sync.aligned.m16n8k16.row.col.f32.f16.f16.f32 "
        "{%0,%1,%2,%3}, {%4,%5,%6,%7}, {%8,%9}, {%0,%1,%2,%3};"
        : "+f"(d[0]), "+f"(d[1]), "+f"(d[2]), "+f"(d[3])
        : "r"(a0), "r"(a1), "r"(a2), "r"(a3), "r"(b0), "r"(b1));
}

__device__ __forceinline__ int wfidx(int wg, int nt, int ks, int lane) {
    int wgOld = wg * 2 + (nt >> 2);
    int ntOld = nt & 3;
    return (((wgOld * 8 + ks) * 4) + ntOld) * 32 + lane;
}

__device__ __forceinline__ void storeTs(uint32_t* img, int f, int t, float v,
                                        int g) {
    float vp = __shfl_xor_sync(0xffffffffu, v, 4);
    if (!(g & 1)) {
        __half2 h2;
        h2.x = __float2half(v);
        h2.y = __float2half(vp);
        img[f * PWA + (wslotA(t) ^ swz(f))] = *(uint32_t*)&h2;
    }
}

// ============================================================================
// kW: build fragment-major operand images
// ============================================================================
__global__ void kW(const float* __restrict__ cw0, const float* __restrict__ cw1,
                   const float* __restrict__ cw2,
                   const float* __restrict__ L10, const float* __restrict__ L20,
                   const float* __restrict__ L11, const float* __restrict__ L21,
                   const float* __restrict__ L12, const float* __restrict__ L22) {
    int b = blockIdx.x;
    if (b < 7) {
        int s, kk;
        if (b == 0)      { s = 0; kk = 0; }
        else if (b < 3)  { s = 1; kk = b - 1; }
        else             { s = 2; kk = b - 3; }
        const float* cw = (s == 0) ? cw0 : (s == 1) ? cw1 : cw2;
        int k = 1 << s;
        uint2* dst = g_Wf[b];
        for (int idx = threadIdx.x; idx < 4096; idx += blockDim.x) {
            int lane = idx & 31;
            int nt = (idx >> 5) & 3;
            int ks = (idx >> 7) & 7;
            int wg = idx >> 10;
            int g = lane >> 2, c = lane & 3;
            int row = wg * 32 + nt * 8 + g;
            int k0 = ks * 16 + 2 * c;
            __half2 b0, b1;
            b0.x = __float2half(cw[(row * 128 + k0) * k + kk]);
            b0.y = __float2half(cw[(row * 128 + k0 + 1) * k + kk]);
            b1.x = __float2half(cw[(row * 128 + k0 + 8) * k + kk]);
            b1.y = __float2half(cw[(row * 128 + k0 + 9) * k + kk]);
            uint2 o;
            o.x = *(uint32_t*)&b0;
            o.y = *(uint32_t*)&b1;
            dst[idx] = o;
        }
    } else {
        int j = b - 7;
        int s = j >> 1, m = j & 1;
        const float* L = (s == 0) ? (m ? L20 : L10)
                       : (s == 1) ? (m ? L21 : L11)
                                  : (m ? L22 : L12);
        int tk = 128 >> s;
        uint4* dst = g_Lf[j];
        for (int idx = threadIdx.x; idx < 2048; idx += blockDim.x) {
            int lane = idx & 31;
            int ks = (idx >> 5) & 7;
            int mt = idx >> 8;
            int g = lane >> 2, c = lane & 3;
            int r0 = mt * 16 + g, r1 = r0 + 8;
            int k0 = ks * 16 + 2 * c;
            float v[8];
#pragma unroll
            for (int e = 0; e < 8; e++) {
                int t = (e & 1) ? r1 : r0;
                int sc = k0 + ((e >> 2) << 3) + ((e >> 1) & 1);
                float vv = 0.0f;
                if ((t / tk) == (sc / tk)) {
                    int tp = t % tk, sp = sc % tk;
                    if (sp <= tp) vv = L[tp * tk + sp];
                }
                v[e] = vv;
            }
            __half2 a0, a1, a2, a3;
            a0.x = __float2half(v[0]); a0.y = __float2half(v[2]);
            a1.x = __float2half(v[1]); a1.y = __float2half(v[3]);
            a2.x = __float2half(v[4]); a2.y = __float2half(v[6]);
            a3.x = __float2half(v[5]); a3.y = __float2half(v[7]);
            uint4 o;
            o.x = *(uint32_t*)&a0;
            o.y = *(uint32_t*)&a1;
            o.z = *(uint32_t*)&a2;
            o.w = *(uint32_t*)&a3;
            dst[idx] = o;
        }
    }
}

// ============================================================================
// run_scale (scrF slot per scale; no trailing barrier)
// ============================================================================
template <int TK, int MT>
__device__ __noinline__ void run_scale(
    int n0, int sbase, int q0, int scIdx,
    const float* __restrict__ lg, const float* __restrict__ lb,
    const uint4* __restrict__ L1f, const uint4* __restrict__ L2f,
    int hoff, const float* __restrict__ cb, float fcb, bool first) {

    constexpr int K = 128 / TK;
    constexpr int NTILE = (MT == 8) ? 2 : 1;
    extern __shared__ uint32_t smw[];
    uint32_t* X  = smw + X_OFF;
    uint32_t* HT = smw + HT_OFF;
    float* scr   = (float*)(smw + SCR_BASE);
    float* s_fcw = scr + 32;
    float* s_cb  = scr + 160;
    float* scrF  = scr + 288 + scIdx * 256;      // private slot per scale

    const int tid = threadIdx.x;
    const int w = tid >> 5, lane = tid & 31;
    const int w3 = w & 3;
    const int wg = w >> 2;
    const int g = lane >> 2, c = lane & 3;
    const int c0 = wg * 64;

    int mta, mtb = 0;
    int myg;
    if (MT == 4) { mta = w3; myg = w3 >> 1; }
    else if (TK == 128) { mta = w3; mtb = 7 - w3; myg = 0; }
    else {
        mta = ((w3 >> 1) << 2) + (w3 & 1);
        mtb = ((w3 >> 1) << 2) + 3 - (w3 & 1);
        myg = w3 >> 1;
    }
    const int ks0 = (myg * TK) >> 4;

    if (first) {
        if (tid < 128) s_cb[tid] = cb[tid];
        __syncthreads();
    }

    auto rowmap = [&](int l, int kk) {
        return (TK == 128) ? (sbase * 128 + l)
                           : ((l / TK) * 128 + (l % TK) * K + kk);
    };

    float accA[8][4], accB[NTILE == 2 ? 8 : 1][4], fcT[2 * NTILE];
#pragma unroll
    for (int i = 0; i < 2 * NTILE; i++) fcT[i] = 0.0f;
#pragma unroll
    for (int nt = 0; nt < 8; nt++)
#pragma unroll
        for (int e = 0; e < 4; e++) accA[nt][e] = 0.0f;
    if (NTILE == 2) {
#pragma unroll
        for (int nt = 0; nt < 8; nt++)
#pragma unroll
            for (int e = 0; e < 4; e++) accB[nt][e] = 0.0f;
    }

    // ---------------- conv: barrier-free over K chunks ----------------
    for (int kk = 0; kk < K; kk++) {
        const uint2* Wf = g_Wf[q0 + kk];
#pragma unroll 2
        for (int ks = 0; ks < 8; ks++) {
            int off = ks * 8 + c * 2;
            uint2 vb[8];
#pragma unroll
            for (int nt = 0; nt < 8; nt++) vb[nt] = Wf[wfidx(wg, nt, ks, lane)];
            int ra0 = rowmap(mta * 16 + g, kk);
            int ra1 = rowmap(mta * 16 + g + 8, kk);
            uint2 ta0 = *(const uint2*)(X + ra0 * PWA + (off ^ swz(ra0)));
            uint2 ta1 = *(const uint2*)(X + ra1 * PWA + (off ^ swz(ra1)));
#pragma unroll
            for (int nt = 0; nt < 8; nt++)
                mma16816(accA[nt], ta0.x, ta1.x, ta0.y, ta1.y, vb[nt].x, vb[nt].y);
            if (NTILE == 2) {
                int rb0 = rowmap(mtb * 16 + g, kk);
                int rb1 = rowmap(mtb * 16 + g + 8, kk);
                uint2 tb0 = *(const uint2*)(X + rb0 * PWA + (off ^ swz(rb0)));
                uint2 tb1 = *(const uint2*)(X + rb1 * PWA + (off ^ swz(rb1)));
#pragma unroll
                for (int nt = 0; nt < 8; nt++)
                    mma16816(accB[nt], tb0.x, tb1.x, tb0.y, tb1.y, vb[nt].x, vb[nt].y);
            }
        }
    }

    // ---------------- LN stats ----------------
    float s = 0.0f, s2 = 0.0f;
#pragma unroll
    for (int ti = 0; ti < NTILE; ti++)
#pragma unroll
        for (int nt = 0; nt < 8; nt++)
#pragma unroll
            for (int e = 0; e < 4; e++) {
                int f = c0 + nt * 8 + (c << 1) + (e & 1);
                float v = (ti ? accB[nt][e] : accA[nt][e]) + s_cb[f];
                s += v; s2 += v * v;
            }
#pragma unroll
    for (int o = 16; o; o >>= 1) {
        s  += __shfl_down_sync(0xffffffffu, s, o);
        s2 += __shfl_down_sync(0xffffffffu, s2, o);
    }
    if (lane == 0) { scr[w] = s; scr[8 + w] = s2; }
    __syncthreads();

    float gs = 0.0f, gs2 = 0.0f;
#pragma unroll
    for (int p = 0; p < 8; p++) {
        int p3 = p & 3;
        int pg = (TK == 128) ? 0 : (p3 >> 1);
        if (pg == myg) { gs += scr[p]; gs2 += scr[8 + p]; }
    }
    const float inv = 1.0f / (float)(TK * 128);
    float mu = gs * inv;
    float var = gs2 * inv - mu * mu;
    float rinv = rsqrtf(var + 1e-5f);

    // ---------------- hT -> HT ; fc conv-part ----------------
#pragma unroll
    for (int ti = 0; ti < NTILE; ti++) {
        int mt = ti ? mtb : mta;
#pragma unroll
        for (int nt = 0; nt < 8; nt++)
#pragma unroll
            for (int eh = 0; eh < 2; eh++) {
                int t = mt * 16 + g + 8 * eh;
                int tl = t & (TK - 1);
                int fb = c0 + nt * 8 + (c << 1);
                float2 lgv = *(const float2*)(lg + tl * 128 + fb);
                float2 lbv = *(const float2*)(lb + tl * 128 + fb);
#pragma unroll
                for (int eo = 0; eo < 2; eo++) {
                    float v = (ti ? accB[nt][eh * 2 + eo] : accA[nt][eh * 2 + eo])
                              + s_cb[fb + eo];
                    fcT[ti * 2 + eh] += v * s_fcw[fb + eo];
                    float hh = (v - mu) * rinv * (eo ? lgv.y : lgv.x)
                               + (eo ? lbv.y : lbv.x);
                    storeTs(HT, fb + eo, t, hh, g);
                }
            }
    }
    __syncthreads();

    // ---------------- GEMM1: u = L1m @ h ----------------
#pragma unroll
    for (int nt = 0; nt < 8; nt++)
#pragma unroll
        for (int e = 0; e < 4; e++) accA[nt][e] = 0.0f;
    if (NTILE == 2) {
#pragma unroll
        for (int nt = 0; nt < 8; nt++)
#pragma unroll
            for (int e = 0; e < 4; e++) accB[nt][e] = 0.0f;
    }
    {
        int kEnd = (NTILE == 2) ? mtb : mta;
        for (int ks = ks0; ks <= kEnd; ks++) {
            int off = ks * 8 + c * 2;
            uint2 vb[8];
#pragma unroll
            for (int nt = 0; nt < 8; nt++) {
                int hr = c0 + nt * 8 + g;
                vb[nt] = *(const uint2*)(HT + hr * PWA + (off ^ swz(hr)));
            }
            if (NTILE == 2) {
                uint4 bv = L1f[(mtb * 8 + ks) * 32 + lane];
#pragma unroll
                for (int nt = 0; nt < 8; nt++)
                    mma16816(accB[nt], bv.x, bv.y, bv.z, bv.w, vb[nt].x, vb[nt].y);
            }
            if (ks <= mta) {
                uint4 av = L1f[(mta * 8 + ks) * 32 + lane];
#pragma unroll
                for (int nt = 0; nt < 8; nt++)
                    mma16816(accA[nt], av.x, av.y, av.z, av.w, vb[nt].x, vb[nt].y);
            }
        }
    }
    __syncthreads();

    // ---------------- uT = hsw(u) -> HT ----------------
#pragma unroll
    for (int ti = 0; ti < NTILE; ti++) {
        int mt = ti ? mtb : mta;
#pragma unroll
        for (int nt = 0; nt < 8; nt++)
#pragma unroll
            for (int e = 0; e < 4; e++) {
                int t = mt * 16 + g + ((e >> 1) << 3);
                int f = c0 + nt * 8 + (c << 1) + (e & 1);
                storeTs(HT, f, t, hswf(ti ? accB[nt][e] : accA[nt][e]), g);
            }
    }
    __syncthreads();

    // ---------------- GEMM2: v = L2m @ u ; fc v-part ----------------
#pragma unroll
    for (int nt = 0; nt < 8; nt++)
#pragma unroll
        for (int e = 0; e < 4; e++) accA[nt][e] = 0.0f;
    if (NTILE == 2) {
#pragma unroll
        for (int nt = 0; nt < 8; nt++)
#pragma unroll
            for (int e = 0; e < 4; e++) accB[nt][e] = 0.0f;
    }
    {
        int kEnd = (NTILE == 2) ? mtb : mta;
        for (int ks = ks0; ks <= kEnd; ks++) {
            int off = ks * 8 + c * 2;
            uint2 vb[8];
#pragma unroll
            for (int nt = 0; nt < 8; nt++) {
                int hr = c0 + nt * 8 + g;
                vb[nt] = *(const uint2*)(HT + hr * PWA + (off ^ swz(hr)));
            }
            if (NTILE == 2) {
                uint4 bv = L2f[(mtb * 8 + ks) * 32 + lane];
#pragma unroll
                for (int nt = 0; nt < 8; nt++)
                    mma16816(accB[nt], bv.x, bv.y, bv.z, bv.w, vb[nt].x, vb[nt].y);
            }
            if (ks <= mta) {
                uint4 av = L2f[(mta * 8 + ks) * 32 + lane];
#pragma unroll
                for (int nt = 0; nt < 8; nt++)
                    mma16816(accA[nt], av.x, av.y, av.z, av.w, vb[nt].x, vb[nt].y);
            }
        }
    }
#pragma unroll
    for (int ti = 0; ti < NTILE; ti++)
#pragma unroll
        for (int nt = 0; nt < 8; nt++)
#pragma unroll
            for (int e = 0; e < 4; e++) {
                int f = c0 + nt * 8 + (c << 1) + (e & 1);
                fcT[ti * 2 + (e >> 1)] +=
                    (ti ? accB[nt][e] : accA[nt][e]) * s_fcw[f];
            }

    // ---------------- fc reduce -> g_h ----------------
#pragma unroll
    for (int i = 0; i < 2 * NTILE; i++) {
        fcT[i] += __shfl_xor_sync(0xffffffffu, fcT[i], 1);
        fcT[i] += __shfl_xor_sync(0xffffffffu, fcT[i], 2);
    }
    if (c == 0) {
#pragma unroll
        for (int i = 0; i < 2 * NTILE; i++) {
            int t = ((i >> 1) ? mtb : mta) * 16 + g + 8 * (i & 1);
            scrF[wg * 128 + t] = fcT[i];
        }
    }
    __syncthreads();
    if (tid < MT * 16) {
        int t = tid;
        float d = scrF[t] + scrF[128 + t];
        g_h[(n0 + sbase + t / TK) * 224 + hoff + (t & (TK - 1))] = d + fcb;
    }
    // no trailing barrier: next scale's writes to scr/HT are all beyond
    // its own first barrier, and each scale uses a private scrF slot.
}

__global__ void __launch_bounds__(NTH, 2) kA12(
    const float* __restrict__ x,
    const float* __restrict__ cb0, const float* __restrict__ lg0,
    const float* __restrict__ lb0,
    const float* __restrict__ cb1, const float* __restrict__ lg1,
    const float* __restrict__ lb1,
    const float* __restrict__ cb2, const float* __restrict__ lg2,
    const float* __restrict__ lb2,
    const float* __restrict__ fcw, const float* __restrict__ fcbp) {
    extern __shared__ uint32_t smw[];
    uint32_t* X = smw + X_OFF;
    float* scr = (float*)(smw + SCR_BASE);
    const int tid = threadIdx.x;
    if (tid < 128) scr[32 + tid] = fcw[tid];
    float fcb = fcbp[0];
    int n0 = blockIdx.x * 2;

    // ---- build X once ----
#pragma unroll 4
    for (int it = 0; it < 32; it++) {
        int idx = it * 256 + tid;
        int r = idx >> 5, f4 = idx & 31;
        const float4 v = ((const float4*)(x +
            ((size_t)(n0 + (r >> 7)) * 128 + (r & 127)) * 128))[f4];
        __half2 h0, h1;
        h0.x = __float2half(v.x); h0.y = __float2half(v.y);
        h1.x = __float2half(v.z); h1.y = __float2half(v.w);
        int k2 = f4 << 2;
        int sw = swz(r);
        X[r * PWA + (wslotA(k2) ^ sw)]     = *(uint32_t*)&h0;
        X[r * PWA + (wslotA(k2 + 2) ^ sw)] = *(uint32_t*)&h1;
    }
    __syncthreads();

    run_scale<128, 8>(n0, 0, 0, 0, lg0, lb0, g_Lf[0], g_Lf[1], 0, cb0, fcb, true);
    run_scale<128, 8>(n0, 1, 0, 1, lg0, lb0, g_Lf[0], g_Lf[1], 0, cb0, fcb, false);
    run_scale<64, 8>(n0, 0, 1, 2, lg1, lb1, g_Lf[2], g_Lf[3], 128, cb1, fcb, true);
    run_scale<32, 4>(n0, 0, 3, 3, lg2, lb2, g_Lf[4], g_Lf[5], 192, cb2, fcb, true);
    __syncthreads();

    // ---- fused kB1: block-local LN partials ----
    float s = 0.0f, s2 = 0.0f;
    for (int i = tid; i < 448; i += 256) {
        float v = g_h[n0 * 224 + i];
        s += v; s2 += v * v;
    }
#pragma unroll
    for (int o = 16; o; o >>= 1) {
        s  += __shfl_down_sync(0xffffffffu, s, o);
        s2 += __shfl_down_sync(0xffffffffu, s2, o);
    }
    float* scrR = scr + 288;             // scale-0 slot is dead now
    int wI = tid >> 5, lI = tid & 31;
    if (lI == 0) { scrR[wI] = s; scrR[8 + wI] = s2; }
    __syncthreads();
    if (tid == 0) {
        float a = 0.0f, b = 0.0f;
#pragma unroll
        for (int i = 0; i < 8; i++) { a += scrR[i]; b += scrR[8 + i]; }
        g_bpart[blockIdx.x] = a;
        g_bpart[2048 + blockIdx.x] = b;
    }
}

// ============================================================================
// phase 2
// ============================================================================
__device__ __forceinline__ void bredsum(float& v, float* scr, int nthr) {
#pragma unroll
    for (int o = 16; o > 0; o >>= 1)
        v += __shfl_down_sync(0xffffffffu, v, o);
    int w = threadIdx.x >> 5, l = threadIdx.x & 31;
    if (l == 0) scr[w] = v;
    __syncthreads();
    if (threadIdx.x == 0) {
        float a = 0.f;
        int nw = (nthr + 31) >> 5;
        for (int i = 0; i < nw; i++) a += scr[i];
        scr[0] = a;
    }
    __syncthreads();
    v = scr[0];
}

// kC1: grid=128, 32 n-rows each; recomputes global stats from g_bpart.
__global__ void kC1(const float* __restrict__ M1,
                    const float* __restrict__ slg,
                    const float* __restrict__ slb) {
    __shared__ float sM1[64 * 32];
    __shared__ float scr[32];
    int j = threadIdx.x;                // 0..223
    int b = blockIdx.x;                 // 0..127
    int n0 = b * 32;

    // stats from g_bpart (L2-hot)
    float s = 0.0f, s2 = 0.0f;
    for (int i = j; i < 2048; i += 224) {
        s  += g_bpart[i];
        s2 += g_bpart[2048 + i];
    }
    bredsum(s, scr, 224);
    __syncthreads();
    bredsum(s2, scr, 224);
    const float inv = 1.0f / (4096.0f * 224.0f);
    float mu = s * inv;
    float var = s2 * inv - mu * mu;
    float rinv = rsqrtf(var + 1e-5f);

    for (int i = j; i < 2048; i += 224) {
        int m = i >> 5, nn = i & 31;
        sM1[i] = M1[m * 4096 + n0 + nn];
    }
    __syncthreads();
    float acc[64];
#pragma unroll
    for (int m = 0; m < 64; m++) acc[m] = 0.f;
#pragma unroll 2
    for (int nn = 0; nn < 32; nn++) {
        int off = (n0 + nn) * 224 + j;
        float hn = (g_h[off] - mu) * rinv * slg[off] + slb[off];
#pragma unroll
        for (int m = 0; m < 64; m++) acc[m] += sM1[m * 32 + nn] * hn;
    }
#pragma unroll
    for (int m = 0; m < 64; m++) g_cpart[(b * 64 + m) * 224 + j] = acc[m];

    // stash stats for kD (block 0 only; deterministic)
    if (b == 0 && j == 0) {
        g_bpart[4095] = mu;          // reuse tail slots (unused by readers)
    }
}

// kC2: reduce 128 partials, hardswish, contract with w2
__global__ void kC2(const float* __restrict__ smw_) {
    int m = blockIdx.x, j = threadIdx.x;
    float g = 0.f;
    for (int b = 0; b < 128; b++) g += g_cpart[(b * 64 + m) * 224 + j];
    float v = hswf(g) * smw_[224 + j];
    __shared__ float scr[32];
    bredsum(v, scr, 224);
    if (threadIdx.x == 0) g_gw[m] = v;
}

__global__ void kD(const float* __restrict__ M2,
                   const float* __restrict__ smw_,
                   const float* __restrict__ smb,
                   float* __restrict__ out) {
    int warp = threadIdx.x >> 5, lane = threadIdx.x & 31;
    int n = blockIdx.x * 8 + warp;
    float acc = 0.f;
    for (int j = lane; j < 224; j += 32)
        acc += g_h[n * 224 + j] * (smw_[j] + smw_[224 + j]);
    for (int m = lane; m < 64; m += 32)
        acc += M2[n * 64 + m] * g_gw[m];
#pragma unroll
    for (int o = 16; o > 0; o >>= 1)
        acc += __shfl_down_sync(0xffffffffu, acc, o);
    if (lane == 0) out[n] = acc + smb[0];
}

// ============================================================================
extern "C" void kernel_launch(void* const* d_in, const int* in_sizes, int n_in,
                              void* d_out, int out_size) {
    const float* x   = (const float*)d_in[0];
    const float* cw0 = (const float*)d_in[1];
    const float* cb0 = (const float*)d_in[2];
    const float* lg0 = (const float*)d_in[3];
    const float* lb0 = (const float*)d_in[4];
    const float* L10 = (const float*)d_in[5];
    const float* L20 = (const float*)d_in[6];
    const float* cw1 = (const float*)d_in[7];
    const float* cb1 = (const float*)d_in[8];
    const float* lg1 = (const float*)d_in[9];
    const float* lb1 = (const float*)d_in[10];
    const float* L11 = (const float*)d_in[11];
    const float* L21 = (const float*)d_in[12];
    const float* cw2 = (const float*)d_in[13];
    const float* cb2 = (const float*)d_in[14];
    const float* lg2 = (const float*)d_in[15];
    const float* lb2 = (const float*)d_in[16];
    const float* L12 = (const float*)d_in[17];
    const float* L22 = (const float*)d_in[18];
    const float* fcw = (const float*)d_in[19];
    const float* fcb = (const float*)d_in[20];
    const float* slg = (const float*)d_in[21];
    const float* slb = (const float*)d_in[22];
    const float* M1  = (const float*)d_in[23];
    const float* M2  = (const float*)d_in[24];
    const float* smw = (const float*)d_in[25];
    const float* smb = (const float*)d_in[26];
    float* out = (float*)d_out;

    cudaFuncSetAttribute(kA12, cudaFuncAttributeMaxDynamicSharedMemorySize,
                         SMEM_SZ);

    kW<<<13, 256>>>(cw0, cw1, cw2, L10, L20, L11, L21, L12, L22);
    kA12<<<2048, NTH, SMEM_SZ>>>(x, cb0, lg0, lb0, cb1, lg1, lb1,
                                 cb2, lg2, lb2, fcw, fcb);
    kC1<<<128, 224>>>(M1, slg, slb);
    kC2<<<64, 224>>>(smw);
    kD<<<512, 256>>>(M2, smw, smb, out);
}

// round 13
// speedup vs baseline: 1.4743x; 1.4743x over previous
#include <cuda_runtime.h>
#include <cuda_fp16.h>
#include <cstdint>

// ============================================================================
// StockMixer GB300 — R13: R12 logic with smem back under the 2-blocks/SM
// budget (113792 B). scrF uses 2 alternating slots instead of 4.
// ============================================================================

#define PWA 72
#define X_OFF  0
#define HT_OFF 18432
#define SCR_BASE 27648
#define SMEM_SZ ((27648 + 800) * 4)     // 113792 B (x2 + reserve <= 228K)

#define NTH 256

// -------------------- device globals --------------------
__device__ __align__(16) uint2 g_Wf[7][4096];
__device__ __align__(16) uint4 g_Lf[6][2048];
__device__ float g_h[4096 * 224];
__device__ float g_bpart[4096];
__device__ float g_cpart[128 * 64 * 224];
__device__ float g_gw[64];

// -------------------- helpers --------------------
__device__ __forceinline__ float hswf(float v) {
    return v * fminf(fmaxf(v + 3.0f, 0.0f), 6.0f) * (1.0f / 6.0f);
}

__device__ __forceinline__ int wslotA(int k) {
    int q = (k >> 1) & 7;
    int pos = ((q & 3) << 1) | (q >> 2);
    return ((k >> 4) << 3) + pos;
}
__device__ __forceinline__ int swz(int r) { return ((r >> 2) & 3) << 3; }

__device__ __forceinline__ void mma16816(float* d, uint32_t a0, uint32_t a1,
                                         uint32_t a2, uint32_t a3,
                                         uint32_t b0, uint32_t b1) {
    asm volatile(
        "mma.sync.aligned.m16n8k16.row.col.f32.f16.f16.f32 "
        "{%0,%1,%2,%3}, {%4,%5,%6,%7}, {%8,%9}, {%0,%1,%2,%3};"
        : "+f"(d[0]), "+f"(d[1]), "+f"(d[2]), "+f"(d[3])
        : "r"(a0), "r"(a1), "r"(a2), "r"(a3), "r"(b0), "r"(b1));
}

__device__ __forceinline__ int wfidx(int wg, int nt, int ks, int lane) {
    int wgOld = wg * 2 + (nt >> 2);
    int ntOld = nt & 3;
    return (((wgOld * 8 + ks) * 4) + ntOld) * 32 + lane;
}

__device__ __forceinline__ void storeTs(uint32_t* img, int f, int t, float v,
                                        int g) {
    float vp = __shfl_xor_sync(0xffffffffu, v, 4);
    if (!(g & 1)) {
        __half2 h2;
        h2.x = __float2half(v);
        h2.y = __float2half(vp);
        img[f * PWA + (wslotA(t) ^ swz(f))] = *(uint32_t*)&h2;
    }
}

// ============================================================================
// kW: build fragment-major operand images
// ============================================================================
__global__ void kW(const float* __restrict__ cw0, const float* __restrict__ cw1,
                   const float* __restrict__ cw2,
                   const float* __restrict__ L10, const float* __restrict__ L20,
                   const float* __restrict__ L11, const float* __restrict__ L21,
                   const float* __restrict__ L12, const float* __restrict__ L22) {
    int b = blockIdx.x;
    if (b < 7) {
        int s, kk;
        if (b == 0)      { s = 0; kk = 0; }
        else if (b < 3)  { s = 1; kk = b - 1; }
        else             { s = 2; kk = b - 3; }
        const float* cw = (s == 0) ? cw0 : (s == 1) ? cw1 : cw2;
        int k = 1 << s;
        uint2* dst = g_Wf[b];
        for (int idx = threadIdx.x; idx < 4096; idx += blockDim.x) {
            int lane = idx & 31;
            int nt = (idx >> 5) & 3;
            int ks = (idx >> 7) & 7;
            int wg = idx >> 10;
            int g = lane >> 2, c = lane & 3;
            int row = wg * 32 + nt * 8 + g;
            int k0 = ks * 16 + 2 * c;
            __half2 b0, b1;
            b0.x = __float2half(cw[(row * 128 + k0) * k + kk]);
            b0.y = __float2half(cw[(row * 128 + k0 + 1) * k + kk]);
            b1.x = __float2half(cw[(row * 128 + k0 + 8) * k + kk]);
            b1.y = __float2half(cw[(row * 128 + k0 + 9) * k + kk]);
            uint2 o;
            o.x = *(uint32_t*)&b0;
            o.y = *(uint32_t*)&b1;
            dst[idx] = o;
        }
    } else {
        int j = b - 7;
        int s = j >> 1, m = j & 1;
        const float* L = (s == 0) ? (m ? L20 : L10)
                       : (s == 1) ? (m ? L21 : L11)
                                  : (m ? L22 : L12);
        int tk = 128 >> s;
        uint4* dst = g_Lf[j];
        for (int idx = threadIdx.x; idx < 2048; idx += blockDim.x) {
            int lane = idx & 31;
            int ks = (idx >> 5) & 7;
            int mt = idx >> 8;
            int g = lane >> 2, c = lane & 3;
            int r0 = mt * 16 + g, r1 = r0 + 8;
            int k0 = ks * 16 + 2 * c;
            float v[8];
#pragma unroll
            for (int e = 0; e < 8; e++) {
                int t = (e & 1) ? r1 : r0;
                int sc = k0 + ((e >> 2) << 3) + ((e >> 1) & 1);
                float vv = 0.0f;
                if ((t / tk) == (sc / tk)) {
                    int tp = t % tk, sp = sc % tk;
                    if (sp <= tp) vv = L[tp * tk + sp];
                }
                v[e] = vv;
            }
            __half2 a0, a1, a2, a3;
            a0.x = __float2half(v[0]); a0.y = __float2half(v[2]);
            a1.x = __float2half(v[1]); a1.y = __float2half(v[3]);
            a2.x = __float2half(v[4]); a2.y = __float2half(v[6]);
            a3.x = __float2half(v[5]); a3.y = __float2half(v[7]);
            uint4 o;
            o.x = *(uint32_t*)&a0;
            o.y = *(uint32_t*)&a1;
            o.z = *(uint32_t*)&a2;
            o.w = *(uint32_t*)&a3;
            dst[idx] = o;
        }
    }
}

// ============================================================================
// run_scale (2 alternating scrF slots; no trailing barrier)
// ============================================================================
template <int TK, int MT>
__device__ __noinline__ void run_scale(
    int n0, int sbase, int q0, int scIdx,
    const float* __restrict__ lg, const float* __restrict__ lb,
    const uint4* __restrict__ L1f, const uint4* __restrict__ L2f,
    int hoff, const float* __restrict__ cb, float fcb, bool first) {

    constexpr int K = 128 / TK;
    constexpr int NTILE = (MT == 8) ? 2 : 1;
    extern __shared__ uint32_t smw[];
    uint32_t* X  = smw + X_OFF;
    uint32_t* HT = smw + HT_OFF;
    float* scr   = (float*)(smw + SCR_BASE);
    float* s_fcw = scr + 32;
    float* s_cb  = scr + 160;
    float* scrF  = scr + 288 + (scIdx & 1) * 256;   // alternating slot

    const int tid = threadIdx.x;
    const int w = tid >> 5, lane = tid & 31;
    const int w3 = w & 3;
    const int wg = w >> 2;
    const int g = lane >> 2, c = lane & 3;
    const int c0 = wg * 64;

    int mta, mtb = 0;
    int myg;
    if (MT == 4) { mta = w3; myg = w3 >> 1; }
    else if (TK == 128) { mta = w3; mtb = 7 - w3; myg = 0; }
    else {
        mta = ((w3 >> 1) << 2) + (w3 & 1);
        mtb = ((w3 >> 1) << 2) + 3 - (w3 & 1);
        myg = w3 >> 1;
    }
    const int ks0 = (myg * TK) >> 4;

    if (first) {
        if (tid < 128) s_cb[tid] = cb[tid];
        __syncthreads();
    }

    auto rowmap = [&](int l, int kk) {
        return (TK == 128) ? (sbase * 128 + l)
                           : ((l / TK) * 128 + (l % TK) * K + kk);
    };

    float accA[8][4], accB[NTILE == 2 ? 8 : 1][4], fcT[2 * NTILE];
#pragma unroll
    for (int i = 0; i < 2 * NTILE; i++) fcT[i] = 0.0f;
#pragma unroll
    for (int nt = 0; nt < 8; nt++)
#pragma unroll
        for (int e = 0; e < 4; e++) accA[nt][e] = 0.0f;
    if (NTILE == 2) {
#pragma unroll
        for (int nt = 0; nt < 8; nt++)
#pragma unroll
            for (int e = 0; e < 4; e++) accB[nt][e] = 0.0f;
    }

    // ---------------- conv: barrier-free over K chunks ----------------
    for (int kk = 0; kk < K; kk++) {
        const uint2* Wf = g_Wf[q0 + kk];
#pragma unroll 2
        for (int ks = 0; ks < 8; ks++) {
            int off = ks * 8 + c * 2;
            uint2 vb[8];
#pragma unroll
            for (int nt = 0; nt < 8; nt++) vb[nt] = Wf[wfidx(wg, nt, ks, lane)];
            int ra0 = rowmap(mta * 16 + g, kk);
            int ra1 = rowmap(mta * 16 + g + 8, kk);
            uint2 ta0 = *(const uint2*)(X + ra0 * PWA + (off ^ swz(ra0)));
            uint2 ta1 = *(const uint2*)(X + ra1 * PWA + (off ^ swz(ra1)));
#pragma unroll
            for (int nt = 0; nt < 8; nt++)
                mma16816(accA[nt], ta0.x, ta1.x, ta0.y, ta1.y, vb[nt].x, vb[nt].y);
            if (NTILE == 2) {
                int rb0 = rowmap(mtb * 16 + g, kk);
                int rb1 = rowmap(mtb * 16 + g + 8, kk);
                uint2 tb0 = *(const uint2*)(X + rb0 * PWA + (off ^ swz(rb0)));
                uint2 tb1 = *(const uint2*)(X + rb1 * PWA + (off ^ swz(rb1)));
#pragma unroll
                for (int nt = 0; nt < 8; nt++)
                    mma16816(accB[nt], tb0.x, tb1.x, tb0.y, tb1.y, vb[nt].x, vb[nt].y);
            }
        }
    }

    // ---------------- LN stats ----------------
    float s = 0.0f, s2 = 0.0f;
#pragma unroll
    for (int ti = 0; ti < NTILE; ti++)
#pragma unroll
        for (int nt = 0; nt < 8; nt++)
#pragma unroll
            for (int e = 0; e < 4; e++) {
                int f = c0 + nt * 8 + (c << 1) + (e & 1);
                float v = (ti ? accB[nt][e] : accA[nt][e]) + s_cb[f];
                s += v; s2 += v * v;
            }
#pragma unroll
    for (int o = 16; o; o >>= 1) {
        s  += __shfl_down_sync(0xffffffffu, s, o);
        s2 += __shfl_down_sync(0xffffffffu, s2, o);
    }
    // sync before writing scr: previous scale's stragglers may still read
    // their scrF slot, but scr (0..15) readers all passed their own barrier.
    __syncthreads();
    if (lane == 0) { scr[w] = s; scr[8 + w] = s2; }
    __syncthreads();

    float gs = 0.0f, gs2 = 0.0f;
#pragma unroll
    for (int p = 0; p < 8; p++) {
        int p3 = p & 3;
        int pg = (TK == 128) ? 0 : (p3 >> 1);
        if (pg == myg) { gs += scr[p]; gs2 += scr[8 + p]; }
    }
    const float inv = 1.0f / (float)(TK * 128);
    float mu = gs * inv;
    float var = gs2 * inv - mu * mu;
    float rinv = rsqrtf(var + 1e-5f);

    // ---------------- hT -> HT ; fc conv-part ----------------
#pragma unroll
    for (int ti = 0; ti < NTILE; ti++) {
        int mt = ti ? mtb : mta;
#pragma unroll
        for (int nt = 0; nt < 8; nt++)
#pragma unroll
            for (int eh = 0; eh < 2; eh++) {
                int t = mt * 16 + g + 8 * eh;
                int tl = t & (TK - 1);
                int fb = c0 + nt * 8 + (c << 1);
                float2 lgv = *(const float2*)(lg + tl * 128 + fb);
                float2 lbv = *(const float2*)(lb + tl * 128 + fb);
#pragma unroll
                for (int eo = 0; eo < 2; eo++) {
                    float v = (ti ? accB[nt][eh * 2 + eo] : accA[nt][eh * 2 + eo])
                              + s_cb[fb + eo];
                    fcT[ti * 2 + eh] += v * s_fcw[fb + eo];
                    float hh = (v - mu) * rinv * (eo ? lgv.y : lgv.x)
                               + (eo ? lbv.y : lbv.x);
                    storeTs(HT, fb + eo, t, hh, g);
                }
            }
    }
    __syncthreads();

    // ---------------- GEMM1: u = L1m @ h ----------------
#pragma unroll
    for (int nt = 0; nt < 8; nt++)
#pragma unroll
        for (int e = 0; e < 4; e++) accA[nt][e] = 0.0f;
    if (NTILE == 2) {
#pragma unroll
        for (int nt = 0; nt < 8; nt++)
#pragma unroll
            for (int e = 0; e < 4; e++) accB[nt][e] = 0.0f;
    }
    {
        int kEnd = (NTILE == 2) ? mtb : mta;
        for (int ks = ks0; ks <= kEnd; ks++) {
            int off = ks * 8 + c * 2;
            uint2 vb[8];
#pragma unroll
            for (int nt = 0; nt < 8; nt++) {
                int hr = c0 + nt * 8 + g;
                vb[nt] = *(const uint2*)(HT + hr * PWA + (off ^ swz(hr)));
            }
            if (NTILE == 2) {
                uint4 bv = L1f[(mtb * 8 + ks) * 32 + lane];
#pragma unroll
                for (int nt = 0; nt < 8; nt++)
                    mma16816(accB[nt], bv.x, bv.y, bv.z, bv.w, vb[nt].x, vb[nt].y);
            }
            if (ks <= mta) {
                uint4 av = L1f[(mta * 8 + ks) * 32 + lane];
#pragma unroll
                for (int nt = 0; nt < 8; nt++)
                    mma16816(accA[nt], av.x, av.y, av.z, av.w, vb[nt].x, vb[nt].y);
            }
        }
    }
    __syncthreads();

    // ---------------- uT = hsw(u) -> HT ----------------
#pragma unroll
    for (int ti = 0; ti < NTILE; ti++) {
        int mt = ti ? mtb : mta;
#pragma unroll
        for (int nt = 0; nt < 8; nt++)
#pragma unroll
            for (int e = 0; e < 4; e++) {
                int t = mt * 16 + g + ((e >> 1) << 3);
                int f = c0 + nt * 8 + (c << 1) + (e & 1);
                storeTs(HT, f, t, hswf(ti ? accB[nt][e] : accA[nt][e]), g);
            }
    }
    __syncthreads();

    // ---------------- GEMM2: v = L2m @ u ; fc v-part ----------------
#pragma unroll
    for (int nt = 0; nt < 8; nt++)
#pragma unroll
        for (int e = 0; e < 4; e++) accA[nt][e] = 0.0f;
    if (NTILE == 2) {
#pragma unroll
        for (int nt = 0; nt < 8; nt++)
#pragma unroll
            for (int e = 0; e < 4; e++) accB[nt][e] = 0.0f;
    }
    {
        int kEnd = (NTILE == 2) ? mtb : mta;
        for (int ks = ks0; ks <= kEnd; ks++) {
            int off = ks * 8 + c * 2;
            uint2 vb[8];
#pragma unroll
            for (int nt = 0; nt < 8; nt++) {
                int hr = c0 + nt * 8 + g;
                vb[nt] = *(const uint2*)(HT + hr * PWA + (off ^ swz(hr)));
            }
            if (NTILE == 2) {
                uint4 bv = L2f[(mtb * 8 + ks) * 32 + lane];
#pragma unroll
                for (int nt = 0; nt < 8; nt++)
                    mma16816(accB[nt], bv.x, bv.y, bv.z, bv.w, vb[nt].x, vb[nt].y);
            }
            if (ks <= mta) {
                uint4 av = L2f[(mta * 8 + ks) * 32 + lane];
#pragma unroll
                for (int nt = 0; nt < 8; nt++)
                    mma16816(accA[nt], av.x, av.y, av.z, av.w, vb[nt].x, vb[nt].y);
            }
        }
    }
#pragma unroll
    for (int ti = 0; ti < NTILE; ti++)
#pragma unroll
        for (int nt = 0; nt < 8; nt++)
#pragma unroll
            for (int e = 0; e < 4; e++) {
                int f = c0 + nt * 8 + (c << 1) + (e & 1);
                fcT[ti * 2 + (e >> 1)] +=
                    (ti ? accB[nt][e] : accA[nt][e]) * s_fcw[f];
            }

    // ---------------- fc reduce -> g_h ----------------
#pragma unroll
    for (int i = 0; i < 2 * NTILE; i++) {
        fcT[i] += __shfl_xor_sync(0xffffffffu, fcT[i], 1);
        fcT[i] += __shfl_xor_sync(0xffffffffu, fcT[i], 2);
    }
    if (c == 0) {
#pragma unroll
        for (int i = 0; i < 2 * NTILE; i++) {
            int t = ((i >> 1) ? mtb : mta) * 16 + g + 8 * (i & 1);
            scrF[wg * 128 + t] = fcT[i];
        }
    }
    __syncthreads();
    if (tid < MT * 16) {
        int t = tid;
        float d = scrF[t] + scrF[128 + t];
        g_h[(n0 + sbase + t / TK) * 224 + hoff + (t & (TK - 1))] = d + fcb;
    }
    // no trailing barrier (alternating scrF slots + leading scr barrier)
}

__global__ void __launch_bounds__(NTH, 2) kA13(
    const float* __restrict__ x,
    const float* __restrict__ cb0, const float* __restrict__ lg0,
    const float* __restrict__ lb0,
    const float* __restrict__ cb1, const float* __restrict__ lg1,
    const float* __restrict__ lb1,
    const float* __restrict__ cb2, const float* __restrict__ lg2,
    const float* __restrict__ lb2,
    const float* __restrict__ fcw, const float* __restrict__ fcbp) {
    extern __shared__ uint32_t smw[];
    uint32_t* X = smw + X_OFF;
    float* scr = (float*)(smw + SCR_BASE);
    const int tid = threadIdx.x;
    if (tid < 128) scr[32 + tid] = fcw[tid];
    float fcb = fcbp[0];
    int n0 = blockIdx.x * 2;

    // ---- build X once ----
#pragma unroll 4
    for (int it = 0; it < 32; it++) {
        int idx = it * 256 + tid;
        int r = idx >> 5, f4 = idx & 31;
        const float4 v = ((const float4*)(x +
            ((size_t)(n0 + (r >> 7)) * 128 + (r & 127)) * 128))[f4];
        __half2 h0, h1;
        h0.x = __float2half(v.x); h0.y = __float2half(v.y);
        h1.x = __float2half(v.z); h1.y = __float2half(v.w);
        int k2 = f4 << 2;
        int sw = swz(r);
        X[r * PWA + (wslotA(k2) ^ sw)]     = *(uint32_t*)&h0;
        X[r * PWA + (wslotA(k2 + 2) ^ sw)] = *(uint32_t*)&h1;
    }
    __syncthreads();

    run_scale<128, 8>(n0, 0, 0, 0, lg0, lb0, g_Lf[0], g_Lf[1], 0, cb0, fcb, true);
    run_scale<128, 8>(n0, 1, 0, 1, lg0, lb0, g_Lf[0], g_Lf[1], 0, cb0, fcb, false);
    run_scale<64, 8>(n0, 0, 1, 2, lg1, lb1, g_Lf[2], g_Lf[3], 128, cb1, fcb, true);
    run_scale<32, 4>(n0, 0, 3, 3, lg2, lb2, g_Lf[4], g_Lf[5], 192, cb2, fcb, true);
    __syncthreads();

    // ---- fused kB1: block-local LN partials ----
    float s = 0.0f, s2 = 0.0f;
    for (int i = tid; i < 448; i += 256) {
        float v = g_h[n0 * 224 + i];
        s += v; s2 += v * v;
    }
#pragma unroll
    for (int o = 16; o; o >>= 1) {
        s  += __shfl_down_sync(0xffffffffu, s, o);
        s2 += __shfl_down_sync(0xffffffffu, s2, o);
    }
    float* scrR = scr + 288;
    int wI = tid >> 5, lI = tid & 31;
    if (lI == 0) { scrR[wI] = s; scrR[8 + wI] = s2; }
    __syncthreads();
    if (tid == 0) {
        float a = 0.0f, b = 0.0f;
#pragma unroll
        for (int i = 0; i < 8; i++) { a += scrR[i]; b += scrR[8 + i]; }
        g_bpart[blockIdx.x] = a;
        g_bpart[2048 + blockIdx.x] = b;
    }
}

// ============================================================================
// phase 2
// ============================================================================
__device__ __forceinline__ void bredsum(float& v, float* scr, int nthr) {
#pragma unroll
    for (int o = 16; o > 0; o >>= 1)
        v += __shfl_down_sync(0xffffffffu, v, o);
    int w = threadIdx.x >> 5, l = threadIdx.x & 31;
    if (l == 0) scr[w] = v;
    __syncthreads();
    if (threadIdx.x == 0) {
        float a = 0.f;
        int nw = (nthr + 31) >> 5;
        for (int i = 0; i < nw; i++) a += scr[i];
        scr[0] = a;
    }
    __syncthreads();
    v = scr[0];
}

// kC1: grid=128, 32 n-rows each; recomputes global LN stats from g_bpart.
__global__ void kC1(const float* __restrict__ M1,
                    const float* __restrict__ slg,
                    const float* __restrict__ slb) {
    __shared__ float sM1[64 * 32];
    __shared__ float scr[32];
    int j = threadIdx.x;                // 0..223
    int b = blockIdx.x;                 // 0..127
    int n0 = b * 32;

    float s = 0.0f, s2 = 0.0f;
    for (int i = j; i < 2048; i += 224) {
        s  += g_bpart[i];
        s2 += g_bpart[2048 + i];
    }
    bredsum(s, scr, 224);
    __syncthreads();
    bredsum(s2, scr, 224);
    const float inv = 1.0f / (4096.0f * 224.0f);
    float mu = s * inv;
    float var = s2 * inv - mu * mu;
    float rinv = rsqrtf(var + 1e-5f);

    for (int i = j; i < 2048; i += 224) {
        int m = i >> 5, nn = i & 31;
        sM1[i] = M1[m * 4096 + n0 + nn];
    }
    __syncthreads();
    float acc[64];
#pragma unroll
    for (int m = 0; m < 64; m++) acc[m] = 0.f;
#pragma unroll 2
    for (int nn = 0; nn < 32; nn++) {
        int off = (n0 + nn) * 224 + j;
        float hn = (g_h[off] - mu) * rinv * slg[off] + slb[off];
#pragma unroll
        for (int m = 0; m < 64; m++) acc[m] += sM1[m * 32 + nn] * hn;
    }
#pragma unroll
    for (int m = 0; m < 64; m++) g_cpart[(b * 64 + m) * 224 + j] = acc[m];
}

// kC2: reduce 128 partials, hardswish, contract with w2
__global__ void kC2(const float* __restrict__ smw_) {
    int m = blockIdx.x, j = threadIdx.x;
    float g = 0.f;
    for (int b = 0; b < 128; b++) g += g_cpart[(b * 64 + m) * 224 + j];
    float v = hswf(g) * smw_[224 + j];
    __shared__ float scr[32];
    bredsum(v, scr, 224);
    if (threadIdx.x == 0) g_gw[m] = v;
}

__global__ void kD(const float* __restrict__ M2,
                   const float* __restrict__ smw_,
                   const float* __restrict__ smb,
                   float* __restrict__ out) {
    int warp = threadIdx.x >> 5, lane = threadIdx.x & 31;
    int n = blockIdx.x * 8 + warp;
    float acc = 0.f;
    for (int j = lane; j < 224; j += 32)
        acc += g_h[n * 224 + j] * (smw_[j] + smw_[224 + j]);
    for (int m = lane; m < 64; m += 32)
        acc += M2[n * 64 + m] * g_gw[m];
#pragma unroll
    for (int o = 16; o > 0; o >>= 1)
        acc += __shfl_down_sync(0xffffffffu, acc, o);
    if (lane == 0) out[n] = acc + smb[0];
}

// ============================================================================
extern "C" void kernel_launch(void* const* d_in, const int* in_sizes, int n_in,
                              void* d_out, int out_size) {
    const float* x   = (const float*)d_in[0];
    const float* cw0 = (const float*)d_in[1];
    const float* cb0 = (const float*)d_in[2];
    const float* lg0 = (const float*)d_in[3];
    const float* lb0 = (const float*)d_in[4];
    const float* L10 = (const float*)d_in[5];
    const float* L20 = (const float*)d_in[6];
    const float* cw1 = (const float*)d_in[7];
    const float* cb1 = (const float*)d_in[8];
    const float* lg1 = (const float*)d_in[9];
    const float* lb1 = (const float*)d_in[10];
    const float* L11 = (const float*)d_in[11];
    const float* L21 = (const float*)d_in[12];
    const float* cw2 = (const float*)d_in[13];
    const float* cb2 = (const float*)d_in[14];
    const float* lg2 = (const float*)d_in[15];
    const float* lb2 = (const float*)d_in[16];
    const float* L12 = (const float*)d_in[17];
    const float* L22 = (const float*)d_in[18];
    const float* fcw = (const float*)d_in[19];
    const float* fcb = (const float*)d_in[20];
    const float* slg = (const float*)d_in[21];
    const float* slb = (const float*)d_in[22];
    const float* M1  = (const float*)d_in[23];
    const float* M2  = (const float*)d_in[24];
    const float* smw = (const float*)d_in[25];
    const float* smb = (const float*)d_in[26];
    float* out = (float*)d_out;

    cudaFuncSetAttribute(kA13, cudaFuncAttributeMaxDynamicSharedMemorySize,
                         SMEM_SZ);

    kW<<<13, 256>>>(cw0, cw1, cw2, L10, L20, L11, L21, L12, L22);
    kA13<<<2048, NTH, SMEM_SZ>>>(x, cb0, lg0, lb0, cb1, lg1, lb1,
                                 cb2, lg2, lb2, fcw, fcb);
    kC1<<<128, 224>>>(M1, slg, slb);
    kC2<<<64, 224>>>(smw);
    kD<<<512, 256>>>(M2, smw, smb, out);
}

// round 14
// speedup vs baseline: 1.4927x; 1.0125x over previous
#include <cuda_runtime.h>
#include <cuda_fp16.h>
#include <cstdint>

// ============================================================================
// StockMixer GB300 — R14: R11's kA verbatim (proven 590 µs) + R13's
// consolidated phase-2 (kB2 folded into kC1, 128-partial kC2).
// ============================================================================

#define PWA 72
#define X_OFF  0                        // 256 rows * 72 words
#define HT_OFF 18432
#define SCR_BASE 27648
#define SMEM_SZ ((27648 + 832) * 4)     // 113920 B (2 blocks/SM, as in R11)

#define NTH 256

// -------------------- device globals --------------------
__device__ __align__(16) uint2 g_Wf[7][4096];   // W fragments (b0,b1)
__device__ __align__(16) uint4 g_Lf[6][2048];   // L fragments (a0..a3)
__device__ float g_h[4096 * 224];
__device__ float g_bpart[4096];                 // [0:2048) sum, [2048:4096) sumsq
__device__ float g_cpart[128 * 64 * 224];       // 7.3 MB partials
__device__ float g_gw[64];

// -------------------- helpers --------------------
__device__ __forceinline__ float hswf(float v) {
    return v * fminf(fmaxf(v + 3.0f, 0.0f), 6.0f) * (1.0f / 6.0f);
}

__device__ __forceinline__ int wslotA(int k) {
    int q = (k >> 1) & 7;
    int pos = ((q & 3) << 1) | (q >> 2);
    return ((k >> 4) << 3) + pos;
}
__device__ __forceinline__ int swz(int r) { return ((r >> 2) & 3) << 3; }

__device__ __forceinline__ void mma16816(float* d, uint32_t a0, uint32_t a1,
                                         uint32_t a2, uint32_t a3,
                                         uint32_t b0, uint32_t b1) {
    asm volatile(
        "mma.sync.aligned.m16n8k16.row.col.f32.f16.f16.f32 "
        "{%0,%1,%2,%3}, {%4,%5,%6,%7}, {%8,%9}, {%0,%1,%2,%3};"
        : "+f"(d[0]), "+f"(d[1]), "+f"(d[2]), "+f"(d[3])
        : "r"(a0), "r"(a1), "r"(a2), "r"(a3), "r"(b0), "r"(b1));
}

__device__ __forceinline__ int wfidx(int wg, int nt, int ks, int lane) {
    int wgOld = wg * 2 + (nt >> 2);
    int ntOld = nt & 3;
    return (((wgOld * 8 + ks) * 4) + ntOld) * 32 + lane;
}

__device__ __forceinline__ void storeTs(uint32_t* img, int f, int t, float v,
                                        int g) {
    float vp = __shfl_xor_sync(0xffffffffu, v, 4);
    if (!(g & 1)) {
        __half2 h2;
        h2.x = __float2half(v);
        h2.y = __float2half(vp);
        img[f * PWA + (wslotA(t) ^ swz(f))] = *(uint32_t*)&h2;
    }
}

// ============================================================================
// kW: build fragment-major operand images
// ============================================================================
__global__ void kW(const float* __restrict__ cw0, const float* __restrict__ cw1,
                   const float* __restrict__ cw2,
                   const float* __restrict__ L10, const float* __restrict__ L20,
                   const float* __restrict__ L11, const float* __restrict__ L21,
                   const float* __restrict__ L12, const float* __restrict__ L22) {
    int b = blockIdx.x;
    if (b < 7) {
        int s, kk;
        if (b == 0)      { s = 0; kk = 0; }
        else if (b < 3)  { s = 1; kk = b - 1; }
        else             { s = 2; kk = b - 3; }
        const float* cw = (s == 0) ? cw0 : (s == 1) ? cw1 : cw2;
        int k = 1 << s;
        uint2* dst = g_Wf[b];
        for (int idx = threadIdx.x; idx < 4096; idx += blockDim.x) {
            int lane = idx & 31;
            int nt = (idx >> 5) & 3;
            int ks = (idx >> 7) & 7;
            int wg = idx >> 10;
            int g = lane >> 2, c = lane & 3;
            int row = wg * 32 + nt * 8 + g;
            int k0 = ks * 16 + 2 * c;
            __half2 b0, b1;
            b0.x = __float2half(cw[(row * 128 + k0) * k + kk]);
            b0.y = __float2half(cw[(row * 128 + k0 + 1) * k + kk]);
            b1.x = __float2half(cw[(row * 128 + k0 + 8) * k + kk]);
            b1.y = __float2half(cw[(row * 128 + k0 + 9) * k + kk]);
            uint2 o;
            o.x = *(uint32_t*)&b0;
            o.y = *(uint32_t*)&b1;
            dst[idx] = o;
        }
    } else {
        int j = b - 7;
        int s = j >> 1, m = j & 1;
        const float* L = (s == 0) ? (m ? L20 : L10)
                       : (s == 1) ? (m ? L21 : L11)
                                  : (m ? L22 : L12);
        int tk = 128 >> s;
        uint4* dst = g_Lf[j];
        for (int idx = threadIdx.x; idx < 2048; idx += blockDim.x) {
            int lane = idx & 31;
            int ks = (idx >> 5) & 7;
            int mt = idx >> 8;
            int g = lane >> 2, c = lane & 3;
            int r0 = mt * 16 + g, r1 = r0 + 8;
            int k0 = ks * 16 + 2 * c;
            float v[8];
#pragma unroll
            for (int e = 0; e < 8; e++) {
                int t = (e & 1) ? r1 : r0;
                int sc = k0 + ((e >> 2) << 3) + ((e >> 1) & 1);
                float vv = 0.0f;
                if ((t / tk) == (sc / tk)) {
                    int tp = t % tk, sp = sc % tk;
                    if (sp <= tp) vv = L[tp * tk + sp];
                }
                v[e] = vv;
            }
            __half2 a0, a1, a2, a3;
            a0.x = __float2half(v[0]); a0.y = __float2half(v[2]);
            a1.x = __float2half(v[1]); a1.y = __float2half(v[3]);
            a2.x = __float2half(v[4]); a2.y = __float2half(v[6]);
            a3.x = __float2half(v[5]); a3.y = __float2half(v[7]);
            uint4 o;
            o.x = *(uint32_t*)&a0;
            o.y = *(uint32_t*)&a1;
            o.z = *(uint32_t*)&a2;
            o.w = *(uint32_t*)&a3;
            dst[idx] = o;
        }
    }
}

// ============================================================================
// run_scale — VERBATIM from R11 (trailing barrier, shared scrF)
// ============================================================================
template <int TK, int MT>
__device__ __noinline__ void run_scale(
    int n0, int sbase, int q0,
    const float* __restrict__ lg, const float* __restrict__ lb,
    const uint4* __restrict__ L1f, const uint4* __restrict__ L2f,
    int hoff, const float* __restrict__ cb, float fcb, bool first) {

    constexpr int K = 128 / TK;
    constexpr int NTILE = (MT == 8) ? 2 : 1;
    extern __shared__ uint32_t smw[];
    uint32_t* X  = smw + X_OFF;
    uint32_t* HT = smw + HT_OFF;
    float* scr   = (float*)(smw + SCR_BASE);
    float* s_fcw = scr + 32;
    float* s_cb  = scr + 160;
    float* scrF  = scr + 288;

    const int tid = threadIdx.x;
    const int w = tid >> 5, lane = tid & 31;
    const int w3 = w & 3;
    const int wg = w >> 2;
    const int g = lane >> 2, c = lane & 3;
    const int c0 = wg * 64;

    int mta, mtb = 0;
    int myg;
    if (MT == 4) { mta = w3; myg = w3 >> 1; }
    else if (TK == 128) { mta = w3; mtb = 7 - w3; myg = 0; }
    else {
        mta = ((w3 >> 1) << 2) + (w3 & 1);
        mtb = ((w3 >> 1) << 2) + 3 - (w3 & 1);
        myg = w3 >> 1;
    }
    const int ks0 = (myg * TK) >> 4;

    if (first) {
        if (tid < 128) s_cb[tid] = cb[tid];
        __syncthreads();
    }

    auto rowmap = [&](int l, int kk) {
        return (TK == 128) ? (sbase * 128 + l)
                           : ((l / TK) * 128 + (l % TK) * K + kk);
    };

    float accA[8][4], accB[NTILE == 2 ? 8 : 1][4], fcT[2 * NTILE];
#pragma unroll
    for (int i = 0; i < 2 * NTILE; i++) fcT[i] = 0.0f;
#pragma unroll
    for (int nt = 0; nt < 8; nt++)
#pragma unroll
        for (int e = 0; e < 4; e++) accA[nt][e] = 0.0f;
    if (NTILE == 2) {
#pragma unroll
        for (int nt = 0; nt < 8; nt++)
#pragma unroll
            for (int e = 0; e < 4; e++) accB[nt][e] = 0.0f;
    }

    // ---------------- conv: barrier-free over K chunks ----------------
    for (int kk = 0; kk < K; kk++) {
        const uint2* Wf = g_Wf[q0 + kk];
#pragma unroll 2
        for (int ks = 0; ks < 8; ks++) {
            int off = ks * 8 + c * 2;
            uint2 vb[8];
#pragma unroll
            for (int nt = 0; nt < 8; nt++) vb[nt] = Wf[wfidx(wg, nt, ks, lane)];
            int ra0 = rowmap(mta * 16 + g, kk);
            int ra1 = rowmap(mta * 16 + g + 8, kk);
            uint2 ta0 = *(const uint2*)(X + ra0 * PWA + (off ^ swz(ra0)));
            uint2 ta1 = *(const uint2*)(X + ra1 * PWA + (off ^ swz(ra1)));
#pragma unroll
            for (int nt = 0; nt < 8; nt++)
                mma16816(accA[nt], ta0.x, ta1.x, ta0.y, ta1.y, vb[nt].x, vb[nt].y);
            if (NTILE == 2) {
                int rb0 = rowmap(mtb * 16 + g, kk);
                int rb1 = rowmap(mtb * 16 + g + 8, kk);
                uint2 tb0 = *(const uint2*)(X + rb0 * PWA + (off ^ swz(rb0)));
                uint2 tb1 = *(const uint2*)(X + rb1 * PWA + (off ^ swz(rb1)));
#pragma unroll
                for (int nt = 0; nt < 8; nt++)
                    mma16816(accB[nt], tb0.x, tb1.x, tb0.y, tb1.y, vb[nt].x, vb[nt].y);
            }
        }
    }

    // ---------------- LN stats ----------------
    float s = 0.0f, s2 = 0.0f;
#pragma unroll
    for (int ti = 0; ti < NTILE; ti++)
#pragma unroll
        for (int nt = 0; nt < 8; nt++)
#pragma unroll
            for (int e = 0; e < 4; e++) {
                int f = c0 + nt * 8 + (c << 1) + (e & 1);
                float v = (ti ? accB[nt][e] : accA[nt][e]) + s_cb[f];
                s += v; s2 += v * v;
            }
#pragma unroll
    for (int o = 16; o; o >>= 1) {
        s  += __shfl_down_sync(0xffffffffu, s, o);
        s2 += __shfl_down_sync(0xffffffffu, s2, o);
    }
    if (lane == 0) { scr[w] = s; scr[8 + w] = s2; }
    __syncthreads();

    float gs = 0.0f, gs2 = 0.0f;
#pragma unroll
    for (int p = 0; p < 8; p++) {
        int p3 = p & 3;
        int pg = (TK == 128) ? 0 : (p3 >> 1);
        if (pg == myg) { gs += scr[p]; gs2 += scr[8 + p]; }
    }
    const float inv = 1.0f / (float)(TK * 128);
    float mu = gs * inv;
    float var = gs2 * inv - mu * mu;
    float rinv = rsqrtf(var + 1e-5f);

    // ---------------- hT -> HT ; fc conv-part ----------------
#pragma unroll
    for (int ti = 0; ti < NTILE; ti++) {
        int mt = ti ? mtb : mta;
#pragma unroll
        for (int nt = 0; nt < 8; nt++)
#pragma unroll
            for (int eh = 0; eh < 2; eh++) {
                int t = mt * 16 + g + 8 * eh;
                int tl = t & (TK - 1);
                int fb = c0 + nt * 8 + (c << 1);
                float2 lgv = *(const float2*)(lg + tl * 128 + fb);
                float2 lbv = *(const float2*)(lb + tl * 128 + fb);
#pragma unroll
                for (int eo = 0; eo < 2; eo++) {
                    float v = (ti ? accB[nt][eh * 2 + eo] : accA[nt][eh * 2 + eo])
                              + s_cb[fb + eo];
                    fcT[ti * 2 + eh] += v * s_fcw[fb + eo];
                    float hh = (v - mu) * rinv * (eo ? lgv.y : lgv.x)
                               + (eo ? lbv.y : lbv.x);
                    storeTs(HT, fb + eo, t, hh, g);
                }
            }
    }
    __syncthreads();

    // ---------------- GEMM1: u = L1m @ h ----------------
#pragma unroll
    for (int nt = 0; nt < 8; nt++)
#pragma unroll
        for (int e = 0; e < 4; e++) accA[nt][e] = 0.0f;
    if (NTILE == 2) {
#pragma unroll
        for (int nt = 0; nt < 8; nt++)
#pragma unroll
            for (int e = 0; e < 4; e++) accB[nt][e] = 0.0f;
    }
    {
        int kEnd = (NTILE == 2) ? mtb : mta;
        for (int ks = ks0; ks <= kEnd; ks++) {
            int off = ks * 8 + c * 2;
            uint2 vb[8];
#pragma unroll
            for (int nt = 0; nt < 8; nt++) {
                int hr = c0 + nt * 8 + g;
                vb[nt] = *(const uint2*)(HT + hr * PWA + (off ^ swz(hr)));
            }
            if (NTILE == 2) {
                uint4 bv = L1f[(mtb * 8 + ks) * 32 + lane];
#pragma unroll
                for (int nt = 0; nt < 8; nt++)
                    mma16816(accB[nt], bv.x, bv.y, bv.z, bv.w, vb[nt].x, vb[nt].y);
            }
            if (ks <= mta) {
                uint4 av = L1f[(mta * 8 + ks) * 32 + lane];
#pragma unroll
                for (int nt = 0; nt < 8; nt++)
                    mma16816(accA[nt], av.x, av.y, av.z, av.w, vb[nt].x, vb[nt].y);
            }
        }
    }
    __syncthreads();

    // ---------------- uT = hsw(u) -> HT ----------------
#pragma unroll
    for (int ti = 0; ti < NTILE; ti++) {
        int mt = ti ? mtb : mta;
#pragma unroll
        for (int nt = 0; nt < 8; nt++)
#pragma unroll
            for (int e = 0; e < 4; e++) {
                int t = mt * 16 + g + ((e >> 1) << 3);
                int f = c0 + nt * 8 + (c << 1) + (e & 1);
                storeTs(HT, f, t, hswf(ti ? accB[nt][e] : accA[nt][e]), g);
            }
    }
    __syncthreads();

    // ---------------- GEMM2: v = L2m @ u ; fc v-part ----------------
#pragma unroll
    for (int nt = 0; nt < 8; nt++)
#pragma unroll
        for (int e = 0; e < 4; e++) accA[nt][e] = 0.0f;
    if (NTILE == 2) {
#pragma unroll
        for (int nt = 0; nt < 8; nt++)
#pragma unroll
            for (int e = 0; e < 4; e++) accB[nt][e] = 0.0f;
    }
    {
        int kEnd = (NTILE == 2) ? mtb : mta;
        for (int ks = ks0; ks <= kEnd; ks++) {
            int off = ks * 8 + c * 2;
            uint2 vb[8];
#pragma unroll
            for (int nt = 0; nt < 8; nt++) {
                int hr = c0 + nt * 8 + g;
                vb[nt] = *(const uint2*)(HT + hr * PWA + (off ^ swz(hr)));
            }
            if (NTILE == 2) {
                uint4 bv = L2f[(mtb * 8 + ks) * 32 + lane];
#pragma unroll
                for (int nt = 0; nt < 8; nt++)
                    mma16816(accB[nt], bv.x, bv.y, bv.z, bv.w, vb[nt].x, vb[nt].y);
            }
            if (ks <= mta) {
                uint4 av = L2f[(mta * 8 + ks) * 32 + lane];
#pragma unroll
                for (int nt = 0; nt < 8; nt++)
                    mma16816(accA[nt], av.x, av.y, av.z, av.w, vb[nt].x, vb[nt].y);
            }
        }
    }
#pragma unroll
    for (int ti = 0; ti < NTILE; ti++)
#pragma unroll
        for (int nt = 0; nt < 8; nt++)
#pragma unroll
            for (int e = 0; e < 4; e++) {
                int f = c0 + nt * 8 + (c << 1) + (e & 1);
                fcT[ti * 2 + (e >> 1)] +=
                    (ti ? accB[nt][e] : accA[nt][e]) * s_fcw[f];
            }

    // ---------------- fc reduce -> g_h ----------------
#pragma unroll
    for (int i = 0; i < 2 * NTILE; i++) {
        fcT[i] += __shfl_xor_sync(0xffffffffu, fcT[i], 1);
        fcT[i] += __shfl_xor_sync(0xffffffffu, fcT[i], 2);
    }
    if (c == 0) {
#pragma unroll
        for (int i = 0; i < 2 * NTILE; i++) {
            int t = ((i >> 1) ? mtb : mta) * 16 + g + 8 * (i & 1);
            scrF[wg * 128 + t] = fcT[i];
        }
    }
    __syncthreads();
    if (tid < MT * 16) {
        int t = tid;
        float d = scrF[t] + scrF[128 + t];
        g_h[(n0 + sbase + t / TK) * 224 + hoff + (t & (TK - 1))] = d + fcb;
    }
    __syncthreads();
}

__global__ void __launch_bounds__(NTH, 2) kA14(
    const float* __restrict__ x,
    const float* __restrict__ cb0, const float* __restrict__ lg0,
    const float* __restrict__ lb0,
    const float* __restrict__ cb1, const float* __restrict__ lg1,
    const float* __restrict__ lb1,
    const float* __restrict__ cb2, const float* __restrict__ lg2,
    const float* __restrict__ lb2,
    const float* __restrict__ fcw, const float* __restrict__ fcbp) {
    extern __shared__ uint32_t smw[];
    uint32_t* X = smw + X_OFF;
    float* scr = (float*)(smw + SCR_BASE);
    const int tid = threadIdx.x;
    if (tid < 128) scr[32 + tid] = fcw[tid];
    float fcb = fcbp[0];
    int n0 = blockIdx.x * 2;

    // ---- build X once ----
#pragma unroll 4
    for (int it = 0; it < 32; it++) {
        int idx = it * 256 + tid;
        int r = idx >> 5, f4 = idx & 31;
        const float4 v = ((const float4*)(x +
            ((size_t)(n0 + (r >> 7)) * 128 + (r & 127)) * 128))[f4];
        __half2 h0, h1;
        h0.x = __float2half(v.x); h0.y = __float2half(v.y);
        h1.x = __float2half(v.z); h1.y = __float2half(v.w);
        int k2 = f4 << 2;
        int sw = swz(r);
        X[r * PWA + (wslotA(k2) ^ sw)]     = *(uint32_t*)&h0;
        X[r * PWA + (wslotA(k2 + 2) ^ sw)] = *(uint32_t*)&h1;
    }
    __syncthreads();

    run_scale<128, 8>(n0, 0, 0, lg0, lb0, g_Lf[0], g_Lf[1], 0, cb0, fcb, true);
    run_scale<128, 8>(n0, 1, 0, lg0, lb0, g_Lf[0], g_Lf[1], 0, cb0, fcb, false);
    run_scale<64, 8>(n0, 0, 1, lg1, lb1, g_Lf[2], g_Lf[3], 128, cb1, fcb, true);
    run_scale<32, 4>(n0, 0, 3, lg2, lb2, g_Lf[4], g_Lf[5], 192, cb2, fcb, true);

    // ---- fused kB1: block-local LN partials ----
    float s = 0.0f, s2 = 0.0f;
    for (int i = tid; i < 448; i += 256) {
        float v = g_h[n0 * 224 + i];
        s += v; s2 += v * v;
    }
#pragma unroll
    for (int o = 16; o; o >>= 1) {
        s  += __shfl_down_sync(0xffffffffu, s, o);
        s2 += __shfl_down_sync(0xffffffffu, s2, o);
    }
    float* scrR = scr + 288;
    int wI = tid >> 5, lI = tid & 31;
    if (lI == 0) { scrR[wI] = s; scrR[8 + wI] = s2; }
    __syncthreads();
    if (tid == 0) {
        float a = 0.0f, b = 0.0f;
#pragma unroll
        for (int i = 0; i < 8; i++) { a += scrR[i]; b += scrR[8 + i]; }
        g_bpart[blockIdx.x] = a;
        g_bpart[2048 + blockIdx.x] = b;
    }
}

// ============================================================================
// phase 2 (R13 consolidated version)
// ============================================================================
__device__ __forceinline__ void bredsum(float& v, float* scr, int nthr) {
#pragma unroll
    for (int o = 16; o > 0; o >>= 1)
        v += __shfl_down_sync(0xffffffffu, v, o);
    int w = threadIdx.x >> 5, l = threadIdx.x & 31;
    if (l == 0) scr[w] = v;
    __syncthreads();
    if (threadIdx.x == 0) {
        float a = 0.f;
        int nw = (nthr + 31) >> 5;
        for (int i = 0; i < nw; i++) a += scr[i];
        scr[0] = a;
    }
    __syncthreads();
    v = scr[0];
}

// kC1: grid=128, 32 n-rows each; computes global LN stats from g_bpart.
__global__ void kC1(const float* __restrict__ M1,
                    const float* __restrict__ slg,
                    const float* __restrict__ slb) {
    __shared__ float sM1[64 * 32];
    __shared__ float scr[32];
    int j = threadIdx.x;                // 0..223
    int b = blockIdx.x;                 // 0..127
    int n0 = b * 32;

    float s = 0.0f, s2 = 0.0f;
    for (int i = j; i < 2048; i += 224) {
        s  += g_bpart[i];
        s2 += g_bpart[2048 + i];
    }
    bredsum(s, scr, 224);
    __syncthreads();
    bredsum(s2, scr, 224);
    const float inv = 1.0f / (4096.0f * 224.0f);
    float mu = s * inv;
    float var = s2 * inv - mu * mu;
    float rinv = rsqrtf(var + 1e-5f);

    for (int i = j; i < 2048; i += 224) {
        int m = i >> 5, nn = i & 31;
        sM1[i] = M1[m * 4096 + n0 + nn];
    }
    __syncthreads();
    float acc[64];
#pragma unroll
    for (int m = 0; m < 64; m++) acc[m] = 0.f;
#pragma unroll 2
    for (int nn = 0; nn < 32; nn++) {
        int off = (n0 + nn) * 224 + j;
        float hn = (g_h[off] - mu) * rinv * slg[off] + slb[off];
#pragma unroll
        for (int m = 0; m < 64; m++) acc[m] += sM1[m * 32 + nn] * hn;
    }
#pragma unroll
    for (int m = 0; m < 64; m++) g_cpart[(b * 64 + m) * 224 + j] = acc[m];
}

// kC2: reduce 128 partials, hardswish, contract with w2
__global__ void kC2(const float* __restrict__ smw_) {
    int m = blockIdx.x, j = threadIdx.x;
    float g = 0.f;
    for (int b = 0; b < 128; b++) g += g_cpart[(b * 64 + m) * 224 + j];
    float v = hswf(g) * smw_[224 + j];
    __shared__ float scr[32];
    bredsum(v, scr, 224);
    if (threadIdx.x == 0) g_gw[m] = v;
}

__global__ void kD(const float* __restrict__ M2,
                   const float* __restrict__ smw_,
                   const float* __restrict__ smb,
                   float* __restrict__ out) {
    int warp = threadIdx.x >> 5, lane = threadIdx.x & 31;
    int n = blockIdx.x * 8 + warp;
    float acc = 0.f;
    for (int j = lane; j < 224; j += 32)
        acc += g_h[n * 224 + j] * (smw_[j] + smw_[224 + j]);
    for (int m = lane; m < 64; m += 32)
        acc += M2[n * 64 + m] * g_gw[m];
#pragma unroll
    for (int o = 16; o > 0; o >>= 1)
        acc += __shfl_down_sync(0xffffffffu, acc, o);
    if (lane == 0) out[n] = acc + smb[0];
}

// ============================================================================
extern "C" void kernel_launch(void* const* d_in, const int* in_sizes, int n_in,
                              void* d_out, int out_size) {
    const float* x   = (const float*)d_in[0];
    const float* cw0 = (const float*)d_in[1];
    const float* cb0 = (const float*)d_in[2];
    const float* lg0 = (const float*)d_in[3];
    const float* lb0 = (const float*)d_in[4];
    const float* L10 = (const float*)d_in[5];
    const float* L20 = (const float*)d_in[6];
    const float* cw1 = (const float*)d_in[7];
    const float* cb1 = (const float*)d_in[8];
    const float* lg1 = (const float*)d_in[9];
    const float* lb1 = (const float*)d_in[10];
    const float* L11 = (const float*)d_in[11];
    const float* L21 = (const float*)d_in[12];
    const float* cw2 = (const float*)d_in[13];
    const float* cb2 = (const float*)d_in[14];
    const float* lg2 = (const float*)d_in[15];
    const float* lb2 = (const float*)d_in[16];
    const float* L12 = (const float*)d_in[17];
    const float* L22 = (const float*)d_in[18];
    const float* fcw = (const float*)d_in[19];
    const float* fcb = (const float*)d_in[20];
    const float* slg = (const float*)d_in[21];
    const float* slb = (const float*)d_in[22];
    const float* M1  = (const float*)d_in[23];
    const float* M2  = (const float*)d_in[24];
    const float* smw = (const float*)d_in[25];
    const float* smb = (const float*)d_in[26];
    float* out = (float*)d_out;

    cudaFuncSetAttribute(kA14, cudaFuncAttributeMaxDynamicSharedMemorySize,
                         SMEM_SZ);

    kW<<<13, 256>>>(cw0, cw1, cw2, L10, L20, L11, L21, L12, L22);
    kA14<<<2048, NTH, SMEM_SZ>>>(x, cb0, lg0, lb0, cb1, lg1, lb1,
                                 cb2, lg2, lb2, fcw, fcb);
    kC1<<<128, 224>>>(M1, slg, slb);
    kC2<<<64, 224>>>(smw);
    kD<<<512, 256>>>(M2, smw, smb, out);
}

// round 15
// speedup vs baseline: 1.4991x; 1.0043x over previous
#include <cuda_runtime.h>
#include <cuda_fp16.h>
#include <cstdint>

// ============================================================================
// StockMixer GB300 — R15: R14's kA byte-identical + latency-unrolled phase-2
// tail (kC1 x4, kC2 x8, kD fully unrolled).
// ============================================================================

#define PWA 72
#define X_OFF  0
#define HT_OFF 18432
#define SCR_BASE 27648
#define SMEM_SZ ((27648 + 832) * 4)     // 113920 B (2 blocks/SM)

#define NTH 256

// -------------------- device globals --------------------
__device__ __align__(16) uint2 g_Wf[7][4096];
__device__ __align__(16) uint4 g_Lf[6][2048];
__device__ float g_h[4096 * 224];
__device__ float g_bpart[4096];
__device__ float g_cpart[128 * 64 * 224];
__device__ float g_gw[64];

// -------------------- helpers --------------------
__device__ __forceinline__ float hswf(float v) {
    return v * fminf(fmaxf(v + 3.0f, 0.0f), 6.0f) * (1.0f / 6.0f);
}

__device__ __forceinline__ int wslotA(int k) {
    int q = (k >> 1) & 7;
    int pos = ((q & 3) << 1) | (q >> 2);
    return ((k >> 4) << 3) + pos;
}
__device__ __forceinline__ int swz(int r) { return ((r >> 2) & 3) << 3; }

__device__ __forceinline__ void mma16816(float* d, uint32_t a0, uint32_t a1,
                                         uint32_t a2, uint32_t a3,
                                         uint32_t b0, uint32_t b1) {
    asm volatile(
        "mma.sync.aligned.m16n8k16.row.col.f32.f16.f16.f32 "
        "{%0,%1,%2,%3}, {%4,%5,%6,%7}, {%8,%9}, {%0,%1,%2,%3};"
        : "+f"(d[0]), "+f"(d[1]), "+f"(d[2]), "+f"(d[3])
        : "r"(a0), "r"(a1), "r"(a2), "r"(a3), "r"(b0), "r"(b1));
}

__device__ __forceinline__ int wfidx(int wg, int nt, int ks, int lane) {
    int wgOld = wg * 2 + (nt >> 2);
    int ntOld = nt & 3;
    return (((wgOld * 8 + ks) * 4) + ntOld) * 32 + lane;
}

__device__ __forceinline__ void storeTs(uint32_t* img, int f, int t, float v,
                                        int g) {
    float vp = __shfl_xor_sync(0xffffffffu, v, 4);
    if (!(g & 1)) {
        __half2 h2;
        h2.x = __float2half(v);
        h2.y = __float2half(vp);
        img[f * PWA + (wslotA(t) ^ swz(f))] = *(uint32_t*)&h2;
    }
}

// ============================================================================
// kW: build fragment-major operand images
// ============================================================================
__global__ void kW(const float* __restrict__ cw0, const float* __restrict__ cw1,
                   const float* __restrict__ cw2,
                   const float* __restrict__ L10, const float* __restrict__ L20,
                   const float* __restrict__ L11, const float* __restrict__ L21,
                   const float* __restrict__ L12, const float* __restrict__ L22) {
    int b = blockIdx.x;
    if (b < 7) {
        int s, kk;
        if (b == 0)      { s = 0; kk = 0; }
        else if (b < 3)  { s = 1; kk = b - 1; }
        else             { s = 2; kk = b - 3; }
        const float* cw = (s == 0) ? cw0 : (s == 1) ? cw1 : cw2;
        int k = 1 << s;
        uint2* dst = g_Wf[b];
        for (int idx = threadIdx.x; idx < 4096; idx += blockDim.x) {
            int lane = idx & 31;
            int nt = (idx >> 5) & 3;
            int ks = (idx >> 7) & 7;
            int wg = idx >> 10;
            int g = lane >> 2, c = lane & 3;
            int row = wg * 32 + nt * 8 + g;
            int k0 = ks * 16 + 2 * c;
            __half2 b0, b1;
            b0.x = __float2half(cw[(row * 128 + k0) * k + kk]);
            b0.y = __float2half(cw[(row * 128 + k0 + 1) * k + kk]);
            b1.x = __float2half(cw[(row * 128 + k0 + 8) * k + kk]);
            b1.y = __float2half(cw[(row * 128 + k0 + 9) * k + kk]);
            uint2 o;
            o.x = *(uint32_t*)&b0;
            o.y = *(uint32_t*)&b1;
            dst[idx] = o;
        }
    } else {
        int j = b - 7;
        int s = j >> 1, m = j & 1;
        const float* L = (s == 0) ? (m ? L20 : L10)
                       : (s == 1) ? (m ? L21 : L11)
                                  : (m ? L22 : L12);
        int tk = 128 >> s;
        uint4* dst = g_Lf[j];
        for (int idx = threadIdx.x; idx < 2048; idx += blockDim.x) {
            int lane = idx & 31;
            int ks = (idx >> 5) & 7;
            int mt = idx >> 8;
            int g = lane >> 2, c = lane & 3;
            int r0 = mt * 16 + g, r1 = r0 + 8;
            int k0 = ks * 16 + 2 * c;
            float v[8];
#pragma unroll
            for (int e = 0; e < 8; e++) {
                int t = (e & 1) ? r1 : r0;
                int sc = k0 + ((e >> 2) << 3) + ((e >> 1) & 1);
                float vv = 0.0f;
                if ((t / tk) == (sc / tk)) {
                    int tp = t % tk, sp = sc % tk;
                    if (sp <= tp) vv = L[tp * tk + sp];
                }
                v[e] = vv;
            }
            __half2 a0, a1, a2, a3;
            a0.x = __float2half(v[0]); a0.y = __float2half(v[2]);
            a1.x = __float2half(v[1]); a1.y = __float2half(v[3]);
            a2.x = __float2half(v[4]); a2.y = __float2half(v[6]);
            a3.x = __float2half(v[5]); a3.y = __float2half(v[7]);
            uint4 o;
            o.x = *(uint32_t*)&a0;
            o.y = *(uint32_t*)&a1;
            o.z = *(uint32_t*)&a2;
            o.w = *(uint32_t*)&a3;
            dst[idx] = o;
        }
    }
}

// ============================================================================
// run_scale — VERBATIM from R11/R14
// ============================================================================
template <int TK, int MT>
__device__ __noinline__ void run_scale(
    int n0, int sbase, int q0,
    const float* __restrict__ lg, const float* __restrict__ lb,
    const uint4* __restrict__ L1f, const uint4* __restrict__ L2f,
    int hoff, const float* __restrict__ cb, float fcb, bool first) {

    constexpr int K = 128 / TK;
    constexpr int NTILE = (MT == 8) ? 2 : 1;
    extern __shared__ uint32_t smw[];
    uint32_t* X  = smw + X_OFF;
    uint32_t* HT = smw + HT_OFF;
    float* scr   = (float*)(smw + SCR_BASE);
    float* s_fcw = scr + 32;
    float* s_cb  = scr + 160;
    float* scrF  = scr + 288;

    const int tid = threadIdx.x;
    const int w = tid >> 5, lane = tid & 31;
    const int w3 = w & 3;
    const int wg = w >> 2;
    const int g = lane >> 2, c = lane & 3;
    const int c0 = wg * 64;

    int mta, mtb = 0;
    int myg;
    if (MT == 4) { mta = w3; myg = w3 >> 1; }
    else if (TK == 128) { mta = w3; mtb = 7 - w3; myg = 0; }
    else {
        mta = ((w3 >> 1) << 2) + (w3 & 1);
        mtb = ((w3 >> 1) << 2) + 3 - (w3 & 1);
        myg = w3 >> 1;
    }
    const int ks0 = (myg * TK) >> 4;

    if (first) {
        if (tid < 128) s_cb[tid] = cb[tid];
        __syncthreads();
    }

    auto rowmap = [&](int l, int kk) {
        return (TK == 128) ? (sbase * 128 + l)
                           : ((l / TK) * 128 + (l % TK) * K + kk);
    };

    float accA[8][4], accB[NTILE == 2 ? 8 : 1][4], fcT[2 * NTILE];
#pragma unroll
    for (int i = 0; i < 2 * NTILE; i++) fcT[i] = 0.0f;
#pragma unroll
    for (int nt = 0; nt < 8; nt++)
#pragma unroll
        for (int e = 0; e < 4; e++) accA[nt][e] = 0.0f;
    if (NTILE == 2) {
#pragma unroll
        for (int nt = 0; nt < 8; nt++)
#pragma unroll
            for (int e = 0; e < 4; e++) accB[nt][e] = 0.0f;
    }

    // ---------------- conv: barrier-free over K chunks ----------------
    for (int kk = 0; kk < K; kk++) {
        const uint2* Wf = g_Wf[q0 + kk];
#pragma unroll 2
        for (int ks = 0; ks < 8; ks++) {
            int off = ks * 8 + c * 2;
            uint2 vb[8];
#pragma unroll
            for (int nt = 0; nt < 8; nt++) vb[nt] = Wf[wfidx(wg, nt, ks, lane)];
            int ra0 = rowmap(mta * 16 + g, kk);
            int ra1 = rowmap(mta * 16 + g + 8, kk);
            uint2 ta0 = *(const uint2*)(X + ra0 * PWA + (off ^ swz(ra0)));
            uint2 ta1 = *(const uint2*)(X + ra1 * PWA + (off ^ swz(ra1)));
#pragma unroll
            for (int nt = 0; nt < 8; nt++)
                mma16816(accA[nt], ta0.x, ta1.x, ta0.y, ta1.y, vb[nt].x, vb[nt].y);
            if (NTILE == 2) {
                int rb0 = rowmap(mtb * 16 + g, kk);
                int rb1 = rowmap(mtb * 16 + g + 8, kk);
                uint2 tb0 = *(const uint2*)(X + rb0 * PWA + (off ^ swz(rb0)));
                uint2 tb1 = *(const uint2*)(X + rb1 * PWA + (off ^ swz(rb1)));
#pragma unroll
                for (int nt = 0; nt < 8; nt++)
                    mma16816(accB[nt], tb0.x, tb1.x, tb0.y, tb1.y, vb[nt].x, vb[nt].y);
            }
        }
    }

    // ---------------- LN stats ----------------
    float s = 0.0f, s2 = 0.0f;
#pragma unroll
    for (int ti = 0; ti < NTILE; ti++)
#pragma unroll
        for (int nt = 0; nt < 8; nt++)
#pragma unroll
            for (int e = 0; e < 4; e++) {
                int f = c0 + nt * 8 + (c << 1) + (e & 1);
                float v = (ti ? accB[nt][e] : accA[nt][e]) + s_cb[f];
                s += v; s2 += v * v;
            }
#pragma unroll
    for (int o = 16; o; o >>= 1) {
        s  += __shfl_down_sync(0xffffffffu, s, o);
        s2 += __shfl_down_sync(0xffffffffu, s2, o);
    }
    if (lane == 0) { scr[w] = s; scr[8 + w] = s2; }
    __syncthreads();

    float gs = 0.0f, gs2 = 0.0f;
#pragma unroll
    for (int p = 0; p < 8; p++) {
        int p3 = p & 3;
        int pg = (TK == 128) ? 0 : (p3 >> 1);
        if (pg == myg) { gs += scr[p]; gs2 += scr[8 + p]; }
    }
    const float inv = 1.0f / (float)(TK * 128);
    float mu = gs * inv;
    float var = gs2 * inv - mu * mu;
    float rinv = rsqrtf(var + 1e-5f);

    // ---------------- hT -> HT ; fc conv-part ----------------
#pragma unroll
    for (int ti = 0; ti < NTILE; ti++) {
        int mt = ti ? mtb : mta;
#pragma unroll
        for (int nt = 0; nt < 8; nt++)
#pragma unroll
            for (int eh = 0; eh < 2; eh++) {
                int t = mt * 16 + g + 8 * eh;
                int tl = t & (TK - 1);
                int fb = c0 + nt * 8 + (c << 1);
                float2 lgv = *(const float2*)(lg + tl * 128 + fb);
                float2 lbv = *(const float2*)(lb + tl * 128 + fb);
#pragma unroll
                for (int eo = 0; eo < 2; eo++) {
                    float v = (ti ? accB[nt][eh * 2 + eo] : accA[nt][eh * 2 + eo])
                              + s_cb[fb + eo];
                    fcT[ti * 2 + eh] += v * s_fcw[fb + eo];
                    float hh = (v - mu) * rinv * (eo ? lgv.y : lgv.x)
                               + (eo ? lbv.y : lbv.x);
                    storeTs(HT, fb + eo, t, hh, g);
                }
            }
    }
    __syncthreads();

    // ---------------- GEMM1: u = L1m @ h ----------------
#pragma unroll
    for (int nt = 0; nt < 8; nt++)
#pragma unroll
        for (int e = 0; e < 4; e++) accA[nt][e] = 0.0f;
    if (NTILE == 2) {
#pragma unroll
        for (int nt = 0; nt < 8; nt++)
#pragma unroll
            for (int e = 0; e < 4; e++) accB[nt][e] = 0.0f;
    }
    {
        int kEnd = (NTILE == 2) ? mtb : mta;
        for (int ks = ks0; ks <= kEnd; ks++) {
            int off = ks * 8 + c * 2;
            uint2 vb[8];
#pragma unroll
            for (int nt = 0; nt < 8; nt++) {
                int hr = c0 + nt * 8 + g;
                vb[nt] = *(const uint2*)(HT + hr * PWA + (off ^ swz(hr)));
            }
            if (NTILE == 2) {
                uint4 bv = L1f[(mtb * 8 + ks) * 32 + lane];
#pragma unroll
                for (int nt = 0; nt < 8; nt++)
                    mma16816(accB[nt], bv.x, bv.y, bv.z, bv.w, vb[nt].x, vb[nt].y);
            }
            if (ks <= mta) {
                uint4 av = L1f[(mta * 8 + ks) * 32 + lane];
#pragma unroll
                for (int nt = 0; nt < 8; nt++)
                    mma16816(accA[nt], av.x, av.y, av.z, av.w, vb[nt].x, vb[nt].y);
            }
        }
    }
    __syncthreads();

    // ---------------- uT = hsw(u) -> HT ----------------
#pragma unroll
    for (int ti = 0; ti < NTILE; ti++) {
        int mt = ti ? mtb : mta;
#pragma unroll
        for (int nt = 0; nt < 8; nt++)
#pragma unroll
            for (int e = 0; e < 4; e++) {
                int t = mt * 16 + g + ((e >> 1) << 3);
                int f = c0 + nt * 8 + (c << 1) + (e & 1);
                storeTs(HT, f, t, hswf(ti ? accB[nt][e] : accA[nt][e]), g);
            }
    }
    __syncthreads();

    // ---------------- GEMM2: v = L2m @ u ; fc v-part ----------------
#pragma unroll
    for (int nt = 0; nt < 8; nt++)
#pragma unroll
        for (int e = 0; e < 4; e++) accA[nt][e] = 0.0f;
    if (NTILE == 2) {
#pragma unroll
        for (int nt = 0; nt < 8; nt++)
#pragma unroll
            for (int e = 0; e < 4; e++) accB[nt][e] = 0.0f;
    }
    {
        int kEnd = (NTILE == 2) ? mtb : mta;
        for (int ks = ks0; ks <= kEnd; ks++) {
            int off = ks * 8 + c * 2;
            uint2 vb[8];
#pragma unroll
            for (int nt = 0; nt < 8; nt++) {
                int hr = c0 + nt * 8 + g;
                vb[nt] = *(const uint2*)(HT + hr * PWA + (off ^ swz(hr)));
            }
            if (NTILE == 2) {
                uint4 bv = L2f[(mtb * 8 + ks) * 32 + lane];
#pragma unroll
                for (int nt = 0; nt < 8; nt++)
                    mma16816(accB[nt], bv.x, bv.y, bv.z, bv.w, vb[nt].x, vb[nt].y);
            }
            if (ks <= mta) {
                uint4 av = L2f[(mta * 8 + ks) * 32 + lane];
#pragma unroll
                for (int nt = 0; nt < 8; nt++)
                    mma16816(accA[nt], av.x, av.y, av.z, av.w, vb[nt].x, vb[nt].y);
            }
        }
    }
#pragma unroll
    for (int ti = 0; ti < NTILE; ti++)
#pragma unroll
        for (int nt = 0; nt < 8; nt++)
#pragma unroll
            for (int e = 0; e < 4; e++) {
                int f = c0 + nt * 8 + (c << 1) + (e & 1);
                fcT[ti * 2 + (e >> 1)] +=
                    (ti ? accB[nt][e] : accA[nt][e]) * s_fcw[f];
            }

    // ---------------- fc reduce -> g_h ----------------
#pragma unroll
    for (int i = 0; i < 2 * NTILE; i++) {
        fcT[i] += __shfl_xor_sync(0xffffffffu, fcT[i], 1);
        fcT[i] += __shfl_xor_sync(0xffffffffu, fcT[i], 2);
    }
    if (c == 0) {
#pragma unroll
        for (int i = 0; i < 2 * NTILE; i++) {
            int t = ((i >> 1) ? mtb : mta) * 16 + g + 8 * (i & 1);
            scrF[wg * 128 + t] = fcT[i];
        }
    }
    __syncthreads();
    if (tid < MT * 16) {
        int t = tid;
        float d = scrF[t] + scrF[128 + t];
        g_h[(n0 + sbase + t / TK) * 224 + hoff + (t & (TK - 1))] = d + fcb;
    }
    __syncthreads();
}

__global__ void __launch_bounds__(NTH, 2) kA15(
    const float* __restrict__ x,
    const float* __restrict__ cb0, const float* __restrict__ lg0,
    const float* __restrict__ lb0,
    const float* __restrict__ cb1, const float* __restrict__ lg1,
    const float* __restrict__ lb1,
    const float* __restrict__ cb2, const float* __restrict__ lg2,
    const float* __restrict__ lb2,
    const float* __restrict__ fcw, const float* __restrict__ fcbp) {
    extern __shared__ uint32_t smw[];
    uint32_t* X = smw + X_OFF;
    float* scr = (float*)(smw + SCR_BASE);
    const int tid = threadIdx.x;
    if (tid < 128) scr[32 + tid] = fcw[tid];
    float fcb = fcbp[0];
    int n0 = blockIdx.x * 2;

    // ---- build X once ----
#pragma unroll 4
    for (int it = 0; it < 32; it++) {
        int idx = it * 256 + tid;
        int r = idx >> 5, f4 = idx & 31;
        const float4 v = ((const float4*)(x +
            ((size_t)(n0 + (r >> 7)) * 128 + (r & 127)) * 128))[f4];
        __half2 h0, h1;
        h0.x = __float2half(v.x); h0.y = __float2half(v.y);
        h1.x = __float2half(v.z); h1.y = __float2half(v.w);
        int k2 = f4 << 2;
        int sw = swz(r);
        X[r * PWA + (wslotA(k2) ^ sw)]     = *(uint32_t*)&h0;
        X[r * PWA + (wslotA(k2 + 2) ^ sw)] = *(uint32_t*)&h1;
    }
    __syncthreads();

    run_scale<128, 8>(n0, 0, 0, lg0, lb0, g_Lf[0], g_Lf[1], 0, cb0, fcb, true);
    run_scale<128, 8>(n0, 1, 0, lg0, lb0, g_Lf[0], g_Lf[1], 0, cb0, fcb, false);
    run_scale<64, 8>(n0, 0, 1, lg1, lb1, g_Lf[2], g_Lf[3], 128, cb1, fcb, true);
    run_scale<32, 4>(n0, 0, 3, lg2, lb2, g_Lf[4], g_Lf[5], 192, cb2, fcb, true);

    // ---- fused kB1: block-local LN partials ----
    float s = 0.0f, s2 = 0.0f;
    for (int i = tid; i < 448; i += 256) {
        float v = g_h[n0 * 224 + i];
        s += v; s2 += v * v;
    }
#pragma unroll
    for (int o = 16; o; o >>= 1) {
        s  += __shfl_down_sync(0xffffffffu, s, o);
        s2 += __shfl_down_sync(0xffffffffu, s2, o);
    }
    float* scrR = scr + 288;
    int wI = tid >> 5, lI = tid & 31;
    if (lI == 0) { scrR[wI] = s; scrR[8 + wI] = s2; }
    __syncthreads();
    if (tid == 0) {
        float a = 0.0f, b = 0.0f;
#pragma unroll
        for (int i = 0; i < 8; i++) { a += scrR[i]; b += scrR[8 + i]; }
        g_bpart[blockIdx.x] = a;
        g_bpart[2048 + blockIdx.x] = b;
    }
}

// ============================================================================
// phase 2
// ============================================================================
__device__ __forceinline__ void bredsum(float& v, float* scr, int nthr) {
#pragma unroll
    for (int o = 16; o > 0; o >>= 1)
        v += __shfl_down_sync(0xffffffffu, v, o);
    int w = threadIdx.x >> 5, l = threadIdx.x & 31;
    if (l == 0) scr[w] = v;
    __syncthreads();
    if (threadIdx.x == 0) {
        float a = 0.f;
        int nw = (nthr + 31) >> 5;
        for (int i = 0; i < nw; i++) a += scr[i];
        scr[0] = a;
    }
    __syncthreads();
    v = scr[0];
}

// kC1: grid=128, 32 n-rows each; computes global LN stats from g_bpart.
__global__ void kC1(const float* __restrict__ M1,
                    const float* __restrict__ slg,
                    const float* __restrict__ slb) {
    __shared__ float sM1[64 * 32];
    __shared__ float scr[32];
    int j = threadIdx.x;                // 0..223
    int b = blockIdx.x;                 // 0..127
    int n0 = b * 32;

    float s = 0.0f, s2 = 0.0f;
    for (int i = j; i < 2048; i += 224) {
        s  += g_bpart[i];
        s2 += g_bpart[2048 + i];
    }
    bredsum(s, scr, 224);
    __syncthreads();
    bredsum(s2, scr, 224);
    const float inv = 1.0f / (4096.0f * 224.0f);
    float mu = s * inv;
    float var = s2 * inv - mu * mu;
    float rinv = rsqrtf(var + 1e-5f);

    for (int i = j; i < 2048; i += 224) {
        int m = i >> 5, nn = i & 31;
        sM1[i] = M1[m * 4096 + n0 + nn];
    }
    __syncthreads();
    float acc[64];
#pragma unroll
    for (int m = 0; m < 64; m++) acc[m] = 0.f;
#pragma unroll 4
    for (int nn = 0; nn < 32; nn++) {
        int off = (n0 + nn) * 224 + j;
        float hn = (g_h[off] - mu) * rinv * slg[off] + slb[off];
#pragma unroll
        for (int m = 0; m < 64; m++) acc[m] += sM1[m * 32 + nn] * hn;
    }
#pragma unroll
    for (int m = 0; m < 64; m++) g_cpart[(b * 64 + m) * 224 + j] = acc[m];
}

// kC2: reduce 128 partials (8-way MLP), hardswish, contract with w2
__global__ void kC2(const float* __restrict__ smw_) {
    int m = blockIdx.x, j = threadIdx.x;
    float g0 = 0.f, g1 = 0.f, g2 = 0.f, g3 = 0.f;
    float g4 = 0.f, g5 = 0.f, g6 = 0.f, g7 = 0.f;
    const float* base = g_cpart + m * 224 + j;
#pragma unroll 4
    for (int b = 0; b < 128; b += 8) {
        g0 += base[(b + 0) * 64 * 224];
        g1 += base[(b + 1) * 64 * 224];
        g2 += base[(b + 2) * 64 * 224];
        g3 += base[(b + 3) * 64 * 224];
        g4 += base[(b + 4) * 64 * 224];
        g5 += base[(b + 5) * 64 * 224];
        g6 += base[(b + 6) * 64 * 224];
        g7 += base[(b + 7) * 64 * 224];
    }
    float g = ((g0 + g1) + (g2 + g3)) + ((g4 + g5) + (g6 + g7));
    float v = hswf(g) * smw_[224 + j];
    __shared__ float scr[32];
    bredsum(v, scr, 224);
    if (threadIdx.x == 0) g_gw[m] = v;
}

__global__ void kD(const float* __restrict__ M2,
                   const float* __restrict__ smw_,
                   const float* __restrict__ smb,
                   float* __restrict__ out) {
    int warp = threadIdx.x >> 5, lane = threadIdx.x & 31;
    int n = blockIdx.x * 8 + warp;
    float acc = 0.f;
#pragma unroll
    for (int i = 0; i < 7; i++) {
        int j = lane + 32 * i;
        acc += g_h[n * 224 + j] * (smw_[j] + smw_[224 + j]);
    }
#pragma unroll
    for (int i = 0; i < 2; i++) {
        int m = lane + 32 * i;
        acc += M2[n * 64 + m] * g_gw[m];
    }
#pragma unroll
    for (int o = 16; o > 0; o >>= 1)
        acc += __shfl_down_sync(0xffffffffu, acc, o);
    if (lane == 0) out[n] = acc + smb[0];
}

// ============================================================================
extern "C" void kernel_launch(void* const* d_in, const int* in_sizes, int n_in,
                              void* d_out, int out_size) {
    const float* x   = (const float*)d_in[0];
    const float* cw0 = (const float*)d_in[1];
    const float* cb0 = (const float*)d_in[2];
    const float* lg0 = (const float*)d_in[3];
    const float* lb0 = (const float*)d_in[4];
    const float* L10 = (const float*)d_in[5];
    const float* L20 = (const float*)d_in[6];
    const float* cw1 = (const float*)d_in[7];
    const float* cb1 = (const float*)d_in[8];
    const float* lg1 = (const float*)d_in[9];
    const float* lb1 = (const float*)d_in[10];
    const float* L11 = (const float*)d_in[11];
    const float* L21 = (const float*)d_in[12];
    const float* cw2 = (const float*)d_in[13];
    const float* cb2 = (const float*)d_in[14];
    const float* lg2 = (const float*)d_in[15];
    const float* lb2 = (const float*)d_in[16];
    const float* L12 = (const float*)d_in[17];
    const float* L22 = (const float*)d_in[18];
    const float* fcw = (const float*)d_in[19];
    const float* fcb = (const float*)d_in[20];
    const float* slg = (const float*)d_in[21];
    const float* slb = (const float*)d_in[22];
    const float* M1  = (const float*)d_in[23];
    const float* M2  = (const float*)d_in[24];
    const float* smw = (const float*)d_in[25];
    const float* smb = (const float*)d_in[26];
    float* out = (float*)d_out;

    cudaFuncSetAttribute(kA15, cudaFuncAttributeMaxDynamicSharedMemorySize,
                         SMEM_SZ);

    kW<<<13, 256>>>(cw0, cw1, cw2, L10, L20, L11, L21, L12, L22);
    kA15<<<2048, NTH, SMEM_SZ>>>(x, cb0, lg0, lb0, cb1, lg1, lb1,
                                 cb2, lg2, lb2, fcw, fcb);
    kC1<<<128, 224>>>(M1, slg, slb);
    kC2<<<64, 224>>>(smw);
    kD<<<512, 256>>>(M2, smw, smb, out);
}

// round 16
// speedup vs baseline: 1.5083x; 1.0061x over previous
#include <cuda_runtime.h>
#include <cuda_fp16.h>
#include <cstdint>

// ============================================================================
// StockMixer GB300 — R16: R14's kA byte-identical; kC1 restructured to
// grid 64 x block 896 producing 64 partials (halved kC2 DRAM traffic).
// ============================================================================

#define PWA 72
#define X_OFF  0
#define HT_OFF 18432
#define SCR_BASE 27648
#define SMEM_SZ ((27648 + 832) * 4)     // 113920 B (2 blocks/SM)

#define NTH 256

// -------------------- device globals --------------------
__device__ __align__(16) uint2 g_Wf[7][4096];
__device__ __align__(16) uint4 g_Lf[6][2048];
__device__ float g_h[4096 * 224];
__device__ float g_bpart[4096];
__device__ float g_cpart[64 * 64 * 224];        // 3.7 MB partials
__device__ float g_gw[64];

// -------------------- helpers --------------------
__device__ __forceinline__ float hswf(float v) {
    return v * fminf(fmaxf(v + 3.0f, 0.0f), 6.0f) * (1.0f / 6.0f);
}

__device__ __forceinline__ int wslotA(int k) {
    int q = (k >> 1) & 7;
    int pos = ((q & 3) << 1) | (q >> 2);
    return ((k >> 4) << 3) + pos;
}
__device__ __forceinline__ int swz(int r) { return ((r >> 2) & 3) << 3; }

__device__ __forceinline__ void mma16816(float* d, uint32_t a0, uint32_t a1,
                                         uint32_t a2, uint32_t a3,
                                         uint32_t b0, uint32_t b1) {
    asm volatile(
        "mma.sync.aligned.m16n8k16.row.col.f32.f16.f16.f32 "
        "{%0,%1,%2,%3}, {%4,%5,%6,%7}, {%8,%9}, {%0,%1,%2,%3};"
        : "+f"(d[0]), "+f"(d[1]), "+f"(d[2]), "+f"(d[3])
        : "r"(a0), "r"(a1), "r"(a2), "r"(a3), "r"(b0), "r"(b1));
}

__device__ __forceinline__ int wfidx(int wg, int nt, int ks, int lane) {
    int wgOld = wg * 2 + (nt >> 2);
    int ntOld = nt & 3;
    return (((wgOld * 8 + ks) * 4) + ntOld) * 32 + lane;
}

__device__ __forceinline__ void storeTs(uint32_t* img, int f, int t, float v,
                                        int g) {
    float vp = __shfl_xor_sync(0xffffffffu, v, 4);
    if (!(g & 1)) {
        __half2 h2;
        h2.x = __float2half(v);
        h2.y = __float2half(vp);
        img[f * PWA + (wslotA(t) ^ swz(f))] = *(uint32_t*)&h2;
    }
}

// ============================================================================
// kW: build fragment-major operand images
// ============================================================================
__global__ void kW(const float* __restrict__ cw0, const float* __restrict__ cw1,
                   const float* __restrict__ cw2,
                   const float* __restrict__ L10, const float* __restrict__ L20,
                   const float* __restrict__ L11, const float* __restrict__ L21,
                   const float* __restrict__ L12, const float* __restrict__ L22) {
    int b = blockIdx.x;
    if (b < 7) {
        int s, kk;
        if (b == 0)      { s = 0; kk = 0; }
        else if (b < 3)  { s = 1; kk = b - 1; }
        else             { s = 2; kk = b - 3; }
        const float* cw = (s == 0) ? cw0 : (s == 1) ? cw1 : cw2;
        int k = 1 << s;
        uint2* dst = g_Wf[b];
        for (int idx = threadIdx.x; idx < 4096; idx += blockDim.x) {
            int lane = idx & 31;
            int nt = (idx >> 5) & 3;
            int ks = (idx >> 7) & 7;
            int wg = idx >> 10;
            int g = lane >> 2, c = lane & 3;
            int row = wg * 32 + nt * 8 + g;
            int k0 = ks * 16 + 2 * c;
            __half2 b0, b1;
            b0.x = __float2half(cw[(row * 128 + k0) * k + kk]);
            b0.y = __float2half(cw[(row * 128 + k0 + 1) * k + kk]);
            b1.x = __float2half(cw[(row * 128 + k0 + 8) * k + kk]);
            b1.y = __float2half(cw[(row * 128 + k0 + 9) * k + kk]);
            uint2 o;
            o.x = *(uint32_t*)&b0;
            o.y = *(uint32_t*)&b1;
            dst[idx] = o;
        }
    } else {
        int j = b - 7;
        int s = j >> 1, m = j & 1;
        const float* L = (s == 0) ? (m ? L20 : L10)
                       : (s == 1) ? (m ? L21 : L11)
                                  : (m ? L22 : L12);
        int tk = 128 >> s;
        uint4* dst = g_Lf[j];
        for (int idx = threadIdx.x; idx < 2048; idx += blockDim.x) {
            int lane = idx & 31;
            int ks = (idx >> 5) & 7;
            int mt = idx >> 8;
            int g = lane >> 2, c = lane & 3;
            int r0 = mt * 16 + g, r1 = r0 + 8;
            int k0 = ks * 16 + 2 * c;
            float v[8];
#pragma unroll
            for (int e = 0; e < 8; e++) {
                int t = (e & 1) ? r1 : r0;
                int sc = k0 + ((e >> 2) << 3) + ((e >> 1) & 1);
                float vv = 0.0f;
                if ((t / tk) == (sc / tk)) {
                    int tp = t % tk, sp = sc % tk;
                    if (sp <= tp) vv = L[tp * tk + sp];
                }
                v[e] = vv;
            }
            __half2 a0, a1, a2, a3;
            a0.x = __float2half(v[0]); a0.y = __float2half(v[2]);
            a1.x = __float2half(v[1]); a1.y = __float2half(v[3]);
            a2.x = __float2half(v[4]); a2.y = __float2half(v[6]);
            a3.x = __float2half(v[5]); a3.y = __float2half(v[7]);
            uint4 o;
            o.x = *(uint32_t*)&a0;
            o.y = *(uint32_t*)&a1;
            o.z = *(uint32_t*)&a2;
            o.w = *(uint32_t*)&a3;
            dst[idx] = o;
        }
    }
}

// ============================================================================
// run_scale — VERBATIM from R11/R14
// ============================================================================
template <int TK, int MT>
__device__ __noinline__ void run_scale(
    int n0, int sbase, int q0,
    const float* __restrict__ lg, const float* __restrict__ lb,
    const uint4* __restrict__ L1f, const uint4* __restrict__ L2f,
    int hoff, const float* __restrict__ cb, float fcb, bool first) {

    constexpr int K = 128 / TK;
    constexpr int NTILE = (MT == 8) ? 2 : 1;
    extern __shared__ uint32_t smw[];
    uint32_t* X  = smw + X_OFF;
    uint32_t* HT = smw + HT_OFF;
    float* scr   = (float*)(smw + SCR_BASE);
    float* s_fcw = scr + 32;
    float* s_cb  = scr + 160;
    float* scrF  = scr + 288;

    const int tid = threadIdx.x;
    const int w = tid >> 5, lane = tid & 31;
    const int w3 = w & 3;
    const int wg = w >> 2;
    const int g = lane >> 2, c = lane & 3;
    const int c0 = wg * 64;

    int mta, mtb = 0;
    int myg;
    if (MT == 4) { mta = w3; myg = w3 >> 1; }
    else if (TK == 128) { mta = w3; mtb = 7 - w3; myg = 0; }
    else {
        mta = ((w3 >> 1) << 2) + (w3 & 1);
        mtb = ((w3 >> 1) << 2) + 3 - (w3 & 1);
        myg = w3 >> 1;
    }
    const int ks0 = (myg * TK) >> 4;

    if (first) {
        if (tid < 128) s_cb[tid] = cb[tid];
        __syncthreads();
    }

    auto rowmap = [&](int l, int kk) {
        return (TK == 128) ? (sbase * 128 + l)
                           : ((l / TK) * 128 + (l % TK) * K + kk);
    };

    float accA[8][4], accB[NTILE == 2 ? 8 : 1][4], fcT[2 * NTILE];
#pragma unroll
    for (int i = 0; i < 2 * NTILE; i++) fcT[i] = 0.0f;
#pragma unroll
    for (int nt = 0; nt < 8; nt++)
#pragma unroll
        for (int e = 0; e < 4; e++) accA[nt][e] = 0.0f;
    if (NTILE == 2) {
#pragma unroll
        for (int nt = 0; nt < 8; nt++)
#pragma unroll
            for (int e = 0; e < 4; e++) accB[nt][e] = 0.0f;
    }

    // ---------------- conv: barrier-free over K chunks ----------------
    for (int kk = 0; kk < K; kk++) {
        const uint2* Wf = g_Wf[q0 + kk];
#pragma unroll 2
        for (int ks = 0; ks < 8; ks++) {
            int off = ks * 8 + c * 2;
            uint2 vb[8];
#pragma unroll
            for (int nt = 0; nt < 8; nt++) vb[nt] = Wf[wfidx(wg, nt, ks, lane)];
            int ra0 = rowmap(mta * 16 + g, kk);
            int ra1 = rowmap(mta * 16 + g + 8, kk);
            uint2 ta0 = *(const uint2*)(X + ra0 * PWA + (off ^ swz(ra0)));
            uint2 ta1 = *(const uint2*)(X + ra1 * PWA + (off ^ swz(ra1)));
#pragma unroll
            for (int nt = 0; nt < 8; nt++)
                mma16816(accA[nt], ta0.x, ta1.x, ta0.y, ta1.y, vb[nt].x, vb[nt].y);
            if (NTILE == 2) {
                int rb0 = rowmap(mtb * 16 + g, kk);
                int rb1 = rowmap(mtb * 16 + g + 8, kk);
                uint2 tb0 = *(const uint2*)(X + rb0 * PWA + (off ^ swz(rb0)));
                uint2 tb1 = *(const uint2*)(X + rb1 * PWA + (off ^ swz(rb1)));
#pragma unroll
                for (int nt = 0; nt < 8; nt++)
                    mma16816(accB[nt], tb0.x, tb1.x, tb0.y, tb1.y, vb[nt].x, vb[nt].y);
            }
        }
    }

    // ---------------- LN stats ----------------
    float s = 0.0f, s2 = 0.0f;
#pragma unroll
    for (int ti = 0; ti < NTILE; ti++)
#pragma unroll
        for (int nt = 0; nt < 8; nt++)
#pragma unroll
            for (int e = 0; e < 4; e++) {
                int f = c0 + nt * 8 + (c << 1) + (e & 1);
                float v = (ti ? accB[nt][e] : accA[nt][e]) + s_cb[f];
                s += v; s2 += v * v;
            }
#pragma unroll
    for (int o = 16; o; o >>= 1) {
        s  += __shfl_down_sync(0xffffffffu, s, o);
        s2 += __shfl_down_sync(0xffffffffu, s2, o);
    }
    if (lane == 0) { scr[w] = s; scr[8 + w] = s2; }
    __syncthreads();

    float gs = 0.0f, gs2 = 0.0f;
#pragma unroll
    for (int p = 0; p < 8; p++) {
        int p3 = p & 3;
        int pg = (TK == 128) ? 0 : (p3 >> 1);
        if (pg == myg) { gs += scr[p]; gs2 += scr[8 + p]; }
    }
    const float inv = 1.0f / (float)(TK * 128);
    float mu = gs * inv;
    float var = gs2 * inv - mu * mu;
    float rinv = rsqrtf(var + 1e-5f);

    // ---------------- hT -> HT ; fc conv-part ----------------
#pragma unroll
    for (int ti = 0; ti < NTILE; ti++) {
        int mt = ti ? mtb : mta;
#pragma unroll
        for (int nt = 0; nt < 8; nt++)
#pragma unroll
            for (int eh = 0; eh < 2; eh++) {
                int t = mt * 16 + g + 8 * eh;
                int tl = t & (TK - 1);
                int fb = c0 + nt * 8 + (c << 1);
                float2 lgv = *(const float2*)(lg + tl * 128 + fb);
                float2 lbv = *(const float2*)(lb + tl * 128 + fb);
#pragma unroll
                for (int eo = 0; eo < 2; eo++) {
                    float v = (ti ? accB[nt][eh * 2 + eo] : accA[nt][eh * 2 + eo])
                              + s_cb[fb + eo];
                    fcT[ti * 2 + eh] += v * s_fcw[fb + eo];
                    float hh = (v - mu) * rinv * (eo ? lgv.y : lgv.x)
                               + (eo ? lbv.y : lbv.x);
                    storeTs(HT, fb + eo, t, hh, g);
                }
            }
    }
    __syncthreads();

    // ---------------- GEMM1: u = L1m @ h ----------------
#pragma unroll
    for (int nt = 0; nt < 8; nt++)
#pragma unroll
        for (int e = 0; e < 4; e++) accA[nt][e] = 0.0f;
    if (NTILE == 2) {
#pragma unroll
        for (int nt = 0; nt < 8; nt++)
#pragma unroll
            for (int e = 0; e < 4; e++) accB[nt][e] = 0.0f;
    }
    {
        int kEnd = (NTILE == 2) ? mtb : mta;
        for (int ks = ks0; ks <= kEnd; ks++) {
            int off = ks * 8 + c * 2;
            uint2 vb[8];
#pragma unroll
            for (int nt = 0; nt < 8; nt++) {
                int hr = c0 + nt * 8 + g;
                vb[nt] = *(const uint2*)(HT + hr * PWA + (off ^ swz(hr)));
            }
            if (NTILE == 2) {
                uint4 bv = L1f[(mtb * 8 + ks) * 32 + lane];
#pragma unroll
                for (int nt = 0; nt < 8; nt++)
                    mma16816(accB[nt], bv.x, bv.y, bv.z, bv.w, vb[nt].x, vb[nt].y);
            }
            if (ks <= mta) {
                uint4 av = L1f[(mta * 8 + ks) * 32 + lane];
#pragma unroll
                for (int nt = 0; nt < 8; nt++)
                    mma16816(accA[nt], av.x, av.y, av.z, av.w, vb[nt].x, vb[nt].y);
            }
        }
    }
    __syncthreads();

    // ---------------- uT = hsw(u) -> HT ----------------
#pragma unroll
    for (int ti = 0; ti < NTILE; ti++) {
        int mt = ti ? mtb : mta;
#pragma unroll
        for (int nt = 0; nt < 8; nt++)
#pragma unroll
            for (int e = 0; e < 4; e++) {
                int t = mt * 16 + g + ((e >> 1) << 3);
                int f = c0 + nt * 8 + (c << 1) + (e & 1);
                storeTs(HT, f, t, hswf(ti ? accB[nt][e] : accA[nt][e]), g);
            }
    }
    __syncthreads();

    // ---------------- GEMM2: v = L2m @ u ; fc v-part ----------------
#pragma unroll
    for (int nt = 0; nt < 8; nt++)
#pragma unroll
        for (int e = 0; e < 4; e++) accA[nt][e] = 0.0f;
    if (NTILE == 2) {
#pragma unroll
        for (int nt = 0; nt < 8; nt++)
#pragma unroll
            for (int e = 0; e < 4; e++) accB[nt][e] = 0.0f;
    }
    {
        int kEnd = (NTILE == 2) ? mtb : mta;
        for (int ks = ks0; ks <= kEnd; ks++) {
            int off = ks * 8 + c * 2;
            uint2 vb[8];
#pragma unroll
            for (int nt = 0; nt < 8; nt++) {
                int hr = c0 + nt * 8 + g;
                vb[nt] = *(const uint2*)(HT + hr * PWA + (off ^ swz(hr)));
            }
            if (NTILE == 2) {
                uint4 bv = L2f[(mtb * 8 + ks) * 32 + lane];
#pragma unroll
                for (int nt = 0; nt < 8; nt++)
                    mma16816(accB[nt], bv.x, bv.y, bv.z, bv.w, vb[nt].x, vb[nt].y);
            }
            if (ks <= mta) {
                uint4 av = L2f[(mta * 8 + ks) * 32 + lane];
#pragma unroll
                for (int nt = 0; nt < 8; nt++)
                    mma16816(accA[nt], av.x, av.y, av.z, av.w, vb[nt].x, vb[nt].y);
            }
        }
    }
#pragma unroll
    for (int ti = 0; ti < NTILE; ti++)
#pragma unroll
        for (int nt = 0; nt < 8; nt++)
#pragma unroll
            for (int e = 0; e < 4; e++) {
                int f = c0 + nt * 8 + (c << 1) + (e & 1);
                fcT[ti * 2 + (e >> 1)] +=
                    (ti ? accB[nt][e] : accA[nt][e]) * s_fcw[f];
            }

    // ---------------- fc reduce -> g_h ----------------
#pragma unroll
    for (int i = 0; i < 2 * NTILE; i++) {
        fcT[i] += __shfl_xor_sync(0xffffffffu, fcT[i], 1);
        fcT[i] += __shfl_xor_sync(0xffffffffu, fcT[i], 2);
    }
    if (c == 0) {
#pragma unroll
        for (int i = 0; i < 2 * NTILE; i++) {
            int t = ((i >> 1) ? mtb : mta) * 16 + g + 8 * (i & 1);
            scrF[wg * 128 + t] = fcT[i];
        }
    }
    __syncthreads();
    if (tid < MT * 16) {
        int t = tid;
        float d = scrF[t] + scrF[128 + t];
        g_h[(n0 + sbase + t / TK) * 224 + hoff + (t & (TK - 1))] = d + fcb;
    }
    __syncthreads();
}

__global__ void __launch_bounds__(NTH, 2) kA16(
    const float* __restrict__ x,
    const float* __restrict__ cb0, const float* __restrict__ lg0,
    const float* __restrict__ lb0,
    const float* __restrict__ cb1, const float* __restrict__ lg1,
    const float* __restrict__ lb1,
    const float* __restrict__ cb2, const float* __restrict__ lg2,
    const float* __restrict__ lb2,
    const float* __restrict__ fcw, const float* __restrict__ fcbp) {
    extern __shared__ uint32_t smw[];
    uint32_t* X = smw + X_OFF;
    float* scr = (float*)(smw + SCR_BASE);
    const int tid = threadIdx.x;
    if (tid < 128) scr[32 + tid] = fcw[tid];
    float fcb = fcbp[0];
    int n0 = blockIdx.x * 2;

    // ---- build X once ----
#pragma unroll 4
    for (int it = 0; it < 32; it++) {
        int idx = it * 256 + tid;
        int r = idx >> 5, f4 = idx & 31;
        const float4 v = ((const float4*)(x +
            ((size_t)(n0 + (r >> 7)) * 128 + (r & 127)) * 128))[f4];
        __half2 h0, h1;
        h0.x = __float2half(v.x); h0.y = __float2half(v.y);
        h1.x = __float2half(v.z); h1.y = __float2half(v.w);
        int k2 = f4 << 2;
        int sw = swz(r);
        X[r * PWA + (wslotA(k2) ^ sw)]     = *(uint32_t*)&h0;
        X[r * PWA + (wslotA(k2 + 2) ^ sw)] = *(uint32_t*)&h1;
    }
    __syncthreads();

    run_scale<128, 8>(n0, 0, 0, lg0, lb0, g_Lf[0], g_Lf[1], 0, cb0, fcb, true);
    run_scale<128, 8>(n0, 1, 0, lg0, lb0, g_Lf[0], g_Lf[1], 0, cb0, fcb, false);
    run_scale<64, 8>(n0, 0, 1, lg1, lb1, g_Lf[2], g_Lf[3], 128, cb1, fcb, true);
    run_scale<32, 4>(n0, 0, 3, lg2, lb2, g_Lf[4], g_Lf[5], 192, cb2, fcb, true);

    // ---- fused kB1: block-local LN partials ----
    float s = 0.0f, s2 = 0.0f;
    for (int i = tid; i < 448; i += 256) {
        float v = g_h[n0 * 224 + i];
        s += v; s2 += v * v;
    }
#pragma unroll
    for (int o = 16; o; o >>= 1) {
        s  += __shfl_down_sync(0xffffffffu, s, o);
        s2 += __shfl_down_sync(0xffffffffu, s2, o);
    }
    float* scrR = scr + 288;
    int wI = tid >> 5, lI = tid & 31;
    if (lI == 0) { scrR[wI] = s; scrR[8 + wI] = s2; }
    __syncthreads();
    if (tid == 0) {
        float a = 0.0f, b = 0.0f;
#pragma unroll
        for (int i = 0; i < 8; i++) { a += scrR[i]; b += scrR[8 + i]; }
        g_bpart[blockIdx.x] = a;
        g_bpart[2048 + blockIdx.x] = b;
    }
}

// ============================================================================
// phase 2
// ============================================================================
__device__ __forceinline__ void bredsum(float& v, float* scr, int nthr) {
#pragma unroll
    for (int o = 16; o > 0; o >>= 1)
        v += __shfl_down_sync(0xffffffffu, v, o);
    int w = threadIdx.x >> 5, l = threadIdx.x & 31;
    if (l == 0) scr[w] = v;
    __syncthreads();
    if (threadIdx.x == 0) {
        float a = 0.f;
        int nw = (nthr + 31) >> 5;
        for (int i = 0; i < nw; i++) a += scr[i];
        scr[0] = a;
    }
    __syncthreads();
    v = scr[0];
}

// kC1: grid=64, block=896 (4 sub-groups of 224). Each block covers 64 n-rows
// and writes ONE 64x224 partial. Stats recomputed from g_bpart in-kernel.
__global__ void __launch_bounds__(896, 1) kC1(
    const float* __restrict__ M1,
    const float* __restrict__ slg,
    const float* __restrict__ slb) {
    __shared__ float sM1[64 * 64];      // 16 KB: M1 tile [m][nn]
    __shared__ float scr[32];
    const int tid = threadIdx.x;
    const int j = tid % 224;            // feature col
    const int mq = tid / 224;           // 0..3: m-range mq*16..mq*16+15
    const int b = blockIdx.x;           // 0..63
    const int n0 = b * 64;

    // global LN stats from g_bpart
    float s = 0.0f, s2 = 0.0f;
    for (int i = tid; i < 2048; i += 896) {
        s  += g_bpart[i];
        s2 += g_bpart[2048 + i];
    }
    bredsum(s, scr, 896);
    __syncthreads();
    bredsum(s2, scr, 896);
    const float inv = 1.0f / (4096.0f * 224.0f);
    float mu = s * inv;
    float var = s2 * inv - mu * mu;
    float rinv = rsqrtf(var + 1e-5f);

    // stage M1 tile [64 m][64 nn]
    for (int i = tid; i < 4096; i += 896) {
        int m = i >> 6, nn = i & 63;
        sM1[i] = M1[m * 4096 + n0 + nn];
    }
    __syncthreads();

    float acc[16];
#pragma unroll
    for (int mi = 0; mi < 16; mi++) acc[mi] = 0.0f;
    const float* sM1q = sM1 + mq * 16 * 64;
#pragma unroll 4
    for (int nn = 0; nn < 64; nn++) {
        int off = (n0 + nn) * 224 + j;
        float hn = (g_h[off] - mu) * rinv * slg[off] + slb[off];
#pragma unroll
        for (int mi = 0; mi < 16; mi++)
            acc[mi] += sM1q[mi * 64 + nn] * hn;
    }
#pragma unroll
    for (int mi = 0; mi < 16; mi++)
        g_cpart[(b * 64 + mq * 16 + mi) * 224 + j] = acc[mi];
}

// kC2: reduce 64 partials, hardswish, contract with w2
__global__ void kC2(const float* __restrict__ smw_) {
    int m = blockIdx.x, j = threadIdx.x;
    float g = 0.f;
    for (int b = 0; b < 64; b++) g += g_cpart[(b * 64 + m) * 224 + j];
    float v = hswf(g) * smw_[224 + j];
    __shared__ float scr[32];
    bredsum(v, scr, 224);
    if (threadIdx.x == 0) g_gw[m] = v;
}

__global__ void kD(const float* __restrict__ M2,
                   const float* __restrict__ smw_,
                   const float* __restrict__ smb,
                   float* __restrict__ out) {
    int warp = threadIdx.x >> 5, lane = threadIdx.x & 31;
    int n = blockIdx.x * 8 + warp;
    float acc = 0.f;
#pragma unroll
    for (int i = 0; i < 7; i++) {
        int j = lane + 32 * i;
        acc += g_h[n * 224 + j] * (smw_[j] + smw_[224 + j]);
    }
#pragma unroll
    for (int i = 0; i < 2; i++) {
        int m = lane + 32 * i;
        acc += M2[n * 64 + m] * g_gw[m];
    }
#pragma unroll
    for (int o = 16; o > 0; o >>= 1)
        acc += __shfl_down_sync(0xffffffffu, acc, o);
    if (lane == 0) out[n] = acc + smb[0];
}

// ============================================================================
extern "C" void kernel_launch(void* const* d_in, const int* in_sizes, int n_in,
                              void* d_out, int out_size) {
    const float* x   = (const float*)d_in[0];
    const float* cw0 = (const float*)d_in[1];
    const float* cb0 = (const float*)d_in[2];
    const float* lg0 = (const float*)d_in[3];
    const float* lb0 = (const float*)d_in[4];
    const float* L10 = (const float*)d_in[5];
    const float* L20 = (const float*)d_in[6];
    const float* cw1 = (const float*)d_in[7];
    const float* cb1 = (const float*)d_in[8];
    const float* lg1 = (const float*)d_in[9];
    const float* lb1 = (const float*)d_in[10];
    const float* L11 = (const float*)d_in[11];
    const float* L21 = (const float*)d_in[12];
    const float* cw2 = (const float*)d_in[13];
    const float* cb2 = (const float*)d_in[14];
    const float* lg2 = (const float*)d_in[15];
    const float* lb2 = (const float*)d_in[16];
    const float* L12 = (const float*)d_in[17];
    const float* L22 = (const float*)d_in[18];
    const float* fcw = (const float*)d_in[19];
    const float* fcb = (const float*)d_in[20];
    const float* slg = (const float*)d_in[21];
    const float* slb = (const float*)d_in[22];
    const float* M1  = (const float*)d_in[23];
    const float* M2  = (const float*)d_in[24];
    const float* smw = (const float*)d_in[25];
    const float* smb = (const float*)d_in[26];
    float* out = (float*)d_out;

    cudaFuncSetAttribute(kA16, cudaFuncAttributeMaxDynamicSharedMemorySize,
                         SMEM_SZ);

    kW<<<13, 256>>>(cw0, cw1, cw2, L10, L20, L11, L21, L12, L22);
    kA16<<<2048, NTH, SMEM_SZ>>>(x, cb0, lg0, lb0, cb1, lg1, lb1,
                                 cb2, lg2, lb2, fcw, fcb);
    kC1<<<64, 896>>>(M1, slg, slb);
    kC2<<<64, 224>>>(smw);
    kD<<<512, 256>>>(M2, smw, smb, out);
}

// round 17
// speedup vs baseline: 1.5125x; 1.0028x over previous
#include <cuda_runtime.h>
#include <cuda_fp16.h>
#include <cstdint>

// ============================================================================
// StockMixer GB300 — R17: R16 with g_cpart transposed to [m][b][j] so kC2
// streams one contiguous 57 KB region per block. kA byte-identical to R14/16.
// ============================================================================

#define PWA 72
#define X_OFF  0
#define HT_OFF 18432
#define SCR_BASE 27648
#define SMEM_SZ ((27648 + 832) * 4)     // 113920 B (2 blocks/SM)

#define NTH 256

// -------------------- device globals --------------------
__device__ __align__(16) uint2 g_Wf[7][4096];
__device__ __align__(16) uint4 g_Lf[6][2048];
__device__ float g_h[4096 * 224];
__device__ float g_bpart[4096];
__device__ float g_cpart[64 * 64 * 224];        // [m][b][j] 3.7 MB
__device__ float g_gw[64];

// -------------------- helpers --------------------
__device__ __forceinline__ float hswf(float v) {
    return v * fminf(fmaxf(v + 3.0f, 0.0f), 6.0f) * (1.0f / 6.0f);
}

__device__ __forceinline__ int wslotA(int k) {
    int q = (k >> 1) & 7;
    int pos = ((q & 3) << 1) | (q >> 2);
    return ((k >> 4) << 3) + pos;
}
__device__ __forceinline__ int swz(int r) { return ((r >> 2) & 3) << 3; }

__device__ __forceinline__ void mma16816(float* d, uint32_t a0, uint32_t a1,
                                         uint32_t a2, uint32_t a3,
                                         uint32_t b0, uint32_t b1) {
    asm volatile(
        "mma.sync.aligned.m16n8k16.row.col.f32.f16.f16.f32 "
        "{%0,%1,%2,%3}, {%4,%5,%6,%7}, {%8,%9}, {%0,%1,%2,%3};"
        : "+f"(d[0]), "+f"(d[1]), "+f"(d[2]), "+f"(d[3])
        : "r"(a0), "r"(a1), "r"(a2), "r"(a3), "r"(b0), "r"(b1));
}

__device__ __forceinline__ int wfidx(int wg, int nt, int ks, int lane) {
    int wgOld = wg * 2 + (nt >> 2);
    int ntOld = nt & 3;
    return (((wgOld * 8 + ks) * 4) + ntOld) * 32 + lane;
}

__device__ __forceinline__ void storeTs(uint32_t* img, int f, int t, float v,
                                        int g) {
    float vp = __shfl_xor_sync(0xffffffffu, v, 4);
    if (!(g & 1)) {
        __half2 h2;
        h2.x = __float2half(v);
        h2.y = __float2half(vp);
        img[f * PWA + (wslotA(t) ^ swz(f))] = *(uint32_t*)&h2;
    }
}

// ============================================================================
// kW: build fragment-major operand images
// ============================================================================
__global__ void kW(const float* __restrict__ cw0, const float* __restrict__ cw1,
                   const float* __restrict__ cw2,
                   const float* __restrict__ L10, const float* __restrict__ L20,
                   const float* __restrict__ L11, const float* __restrict__ L21,
                   const float* __restrict__ L12, const float* __restrict__ L22) {
    int b = blockIdx.x;
    if (b < 7) {
        int s, kk;
        if (b == 0)      { s = 0; kk = 0; }
        else if (b < 3)  { s = 1; kk = b - 1; }
        else             { s = 2; kk = b - 3; }
        const float* cw = (s == 0) ? cw0 : (s == 1) ? cw1 : cw2;
        int k = 1 << s;
        uint2* dst = g_Wf[b];
        for (int idx = threadIdx.x; idx < 4096; idx += blockDim.x) {
            int lane = idx & 31;
            int nt = (idx >> 5) & 3;
            int ks = (idx >> 7) & 7;
            int wg = idx >> 10;
            int g = lane >> 2, c = lane & 3;
            int row = wg * 32 + nt * 8 + g;
            int k0 = ks * 16 + 2 * c;
            __half2 b0, b1;
            b0.x = __float2half(cw[(row * 128 + k0) * k + kk]);
            b0.y = __float2half(cw[(row * 128 + k0 + 1) * k + kk]);
            b1.x = __float2half(cw[(row * 128 + k0 + 8) * k + kk]);
            b1.y = __float2half(cw[(row * 128 + k0 + 9) * k + kk]);
            uint2 o;
            o.x = *(uint32_t*)&b0;
            o.y = *(uint32_t*)&b1;
            dst[idx] = o;
        }
    } else {
        int j = b - 7;
        int s = j >> 1, m = j & 1;
        const float* L = (s == 0) ? (m ? L20 : L10)
                       : (s == 1) ? (m ? L21 : L11)
                                  : (m ? L22 : L12);
        int tk = 128 >> s;
        uint4* dst = g_Lf[j];
        for (int idx = threadIdx.x; idx < 2048; idx += blockDim.x) {
            int lane = idx & 31;
            int ks = (idx >> 5) & 7;
            int mt = idx >> 8;
            int g = lane >> 2, c = lane & 3;
            int r0 = mt * 16 + g, r1 = r0 + 8;
            int k0 = ks * 16 + 2 * c;
            float v[8];
#pragma unroll
            for (int e = 0; e < 8; e++) {
                int t = (e & 1) ? r1 : r0;
                int sc = k0 + ((e >> 2) << 3) + ((e >> 1) & 1);
                float vv = 0.0f;
                if ((t / tk) == (sc / tk)) {
                    int tp = t % tk, sp = sc % tk;
                    if (sp <= tp) vv = L[tp * tk + sp];
                }
                v[e] = vv;
            }
            __half2 a0, a1, a2, a3;
            a0.x = __float2half(v[0]); a0.y = __float2half(v[2]);
            a1.x = __float2half(v[1]); a1.y = __float2half(v[3]);
            a2.x = __float2half(v[4]); a2.y = __float2half(v[6]);
            a3.x = __float2half(v[5]); a3.y = __float2half(v[7]);
            uint4 o;
            o.x = *(uint32_t*)&a0;
            o.y = *(uint32_t*)&a1;
            o.z = *(uint32_t*)&a2;
            o.w = *(uint32_t*)&a3;
            dst[idx] = o;
        }
    }
}

// ============================================================================
// run_scale — VERBATIM from R11/R14/R16
// ============================================================================
template <int TK, int MT>
__device__ __noinline__ void run_scale(
    int n0, int sbase, int q0,
    const float* __restrict__ lg, const float* __restrict__ lb,
    const uint4* __restrict__ L1f, const uint4* __restrict__ L2f,
    int hoff, const float* __restrict__ cb, float fcb, bool first) {

    constexpr int K = 128 / TK;
    constexpr int NTILE = (MT == 8) ? 2 : 1;
    extern __shared__ uint32_t smw[];
    uint32_t* X  = smw + X_OFF;
    uint32_t* HT = smw + HT_OFF;
    float* scr   = (float*)(smw + SCR_BASE);
    float* s_fcw = scr + 32;
    float* s_cb  = scr + 160;
    float* scrF  = scr + 288;

    const int tid = threadIdx.x;
    const int w = tid >> 5, lane = tid & 31;
    const int w3 = w & 3;
    const int wg = w >> 2;
    const int g = lane >> 2, c = lane & 3;
    const int c0 = wg * 64;

    int mta, mtb = 0;
    int myg;
    if (MT == 4) { mta = w3; myg = w3 >> 1; }
    else if (TK == 128) { mta = w3; mtb = 7 - w3; myg = 0; }
    else {
        mta = ((w3 >> 1) << 2) + (w3 & 1);
        mtb = ((w3 >> 1) << 2) + 3 - (w3 & 1);
        myg = w3 >> 1;
    }
    const int ks0 = (myg * TK) >> 4;

    if (first) {
        if (tid < 128) s_cb[tid] = cb[tid];
        __syncthreads();
    }

    auto rowmap = [&](int l, int kk) {
        return (TK == 128) ? (sbase * 128 + l)
                           : ((l / TK) * 128 + (l % TK) * K + kk);
    };

    float accA[8][4], accB[NTILE == 2 ? 8 : 1][4], fcT[2 * NTILE];
#pragma unroll
    for (int i = 0; i < 2 * NTILE; i++) fcT[i] = 0.0f;
#pragma unroll
    for (int nt = 0; nt < 8; nt++)
#pragma unroll
        for (int e = 0; e < 4; e++) accA[nt][e] = 0.0f;
    if (NTILE == 2) {
#pragma unroll
        for (int nt = 0; nt < 8; nt++)
#pragma unroll
            for (int e = 0; e < 4; e++) accB[nt][e] = 0.0f;
    }

    // ---------------- conv: barrier-free over K chunks ----------------
    for (int kk = 0; kk < K; kk++) {
        const uint2* Wf = g_Wf[q0 + kk];
#pragma unroll 2
        for (int ks = 0; ks < 8; ks++) {
            int off = ks * 8 + c * 2;
            uint2 vb[8];
#pragma unroll
            for (int nt = 0; nt < 8; nt++) vb[nt] = Wf[wfidx(wg, nt, ks, lane)];
            int ra0 = rowmap(mta * 16 + g, kk);
            int ra1 = rowmap(mta * 16 + g + 8, kk);
            uint2 ta0 = *(const uint2*)(X + ra0 * PWA + (off ^ swz(ra0)));
            uint2 ta1 = *(const uint2*)(X + ra1 * PWA + (off ^ swz(ra1)));
#pragma unroll
            for (int nt = 0; nt < 8; nt++)
                mma16816(accA[nt], ta0.x, ta1.x, ta0.y, ta1.y, vb[nt].x, vb[nt].y);
            if (NTILE == 2) {
                int rb0 = rowmap(mtb * 16 + g, kk);
                int rb1 = rowmap(mtb * 16 + g + 8, kk);
                uint2 tb0 = *(const uint2*)(X + rb0 * PWA + (off ^ swz(rb0)));
                uint2 tb1 = *(const uint2*)(X + rb1 * PWA + (off ^ swz(rb1)));
#pragma unroll
                for (int nt = 0; nt < 8; nt++)
                    mma16816(accB[nt], tb0.x, tb1.x, tb0.y, tb1.y, vb[nt].x, vb[nt].y);
            }
        }
    }

    // ---------------- LN stats ----------------
    float s = 0.0f, s2 = 0.0f;
#pragma unroll
    for (int ti = 0; ti < NTILE; ti++)
#pragma unroll
        for (int nt = 0; nt < 8; nt++)
#pragma unroll
            for (int e = 0; e < 4; e++) {
                int f = c0 + nt * 8 + (c << 1) + (e & 1);
                float v = (ti ? accB[nt][e] : accA[nt][e]) + s_cb[f];
                s += v; s2 += v * v;
            }
#pragma unroll
    for (int o = 16; o; o >>= 1) {
        s  += __shfl_down_sync(0xffffffffu, s, o);
        s2 += __shfl_down_sync(0xffffffffu, s2, o);
    }
    if (lane == 0) { scr[w] = s; scr[8 + w] = s2; }
    __syncthreads();

    float gs = 0.0f, gs2 = 0.0f;
#pragma unroll
    for (int p = 0; p < 8; p++) {
        int p3 = p & 3;
        int pg = (TK == 128) ? 0 : (p3 >> 1);
        if (pg == myg) { gs += scr[p]; gs2 += scr[8 + p]; }
    }
    const float inv = 1.0f / (float)(TK * 128);
    float mu = gs * inv;
    float var = gs2 * inv - mu * mu;
    float rinv = rsqrtf(var + 1e-5f);

    // ---------------- hT -> HT ; fc conv-part ----------------
#pragma unroll
    for (int ti = 0; ti < NTILE; ti++) {
        int mt = ti ? mtb : mta;
#pragma unroll
        for (int nt = 0; nt < 8; nt++)
#pragma unroll
            for (int eh = 0; eh < 2; eh++) {
                int t = mt * 16 + g + 8 * eh;
                int tl = t & (TK - 1);
                int fb = c0 + nt * 8 + (c << 1);
                float2 lgv = *(const float2*)(lg + tl * 128 + fb);
                float2 lbv = *(const float2*)(lb + tl * 128 + fb);
#pragma unroll
                for (int eo = 0; eo < 2; eo++) {
                    float v = (ti ? accB[nt][eh * 2 + eo] : accA[nt][eh * 2 + eo])
                              + s_cb[fb + eo];
                    fcT[ti * 2 + eh] += v * s_fcw[fb + eo];
                    float hh = (v - mu) * rinv * (eo ? lgv.y : lgv.x)
                               + (eo ? lbv.y : lbv.x);
                    storeTs(HT, fb + eo, t, hh, g);
                }
            }
    }
    __syncthreads();

    // ---------------- GEMM1: u = L1m @ h ----------------
#pragma unroll
    for (int nt = 0; nt < 8; nt++)
#pragma unroll
        for (int e = 0; e < 4; e++) accA[nt][e] = 0.0f;
    if (NTILE == 2) {
#pragma unroll
        for (int nt = 0; nt < 8; nt++)
#pragma unroll
            for (int e = 0; e < 4; e++) accB[nt][e] = 0.0f;
    }
    {
        int kEnd = (NTILE == 2) ? mtb : mta;
        for (int ks = ks0; ks <= kEnd; ks++) {
            int off = ks * 8 + c * 2;
            uint2 vb[8];
#pragma unroll
            for (int nt = 0; nt < 8; nt++) {
                int hr = c0 + nt * 8 + g;
                vb[nt] = *(const uint2*)(HT + hr * PWA + (off ^ swz(hr)));
            }
            if (NTILE == 2) {
                uint4 bv = L1f[(mtb * 8 + ks) * 32 + lane];
#pragma unroll
                for (int nt = 0; nt < 8; nt++)
                    mma16816(accB[nt], bv.x, bv.y, bv.z, bv.w, vb[nt].x, vb[nt].y);
            }
            if (ks <= mta) {
                uint4 av = L1f[(mta * 8 + ks) * 32 + lane];
#pragma unroll
                for (int nt = 0; nt < 8; nt++)
                    mma16816(accA[nt], av.x, av.y, av.z, av.w, vb[nt].x, vb[nt].y);
            }
        }
    }
    __syncthreads();

    // ---------------- uT = hsw(u) -> HT ----------------
#pragma unroll
    for (int ti = 0; ti < NTILE; ti++) {
        int mt = ti ? mtb : mta;
#pragma unroll
        for (int nt = 0; nt < 8; nt++)
#pragma unroll
            for (int e = 0; e < 4; e++) {
                int t = mt * 16 + g + ((e >> 1) << 3);
                int f = c0 + nt * 8 + (c << 1) + (e & 1);
                storeTs(HT, f, t, hswf(ti ? accB[nt][e] : accA[nt][e]), g);
            }
    }
    __syncthreads();

    // ---------------- GEMM2: v = L2m @ u ; fc v-part ----------------
#pragma unroll
    for (int nt = 0; nt < 8; nt++)
#pragma unroll
        for (int e = 0; e < 4; e++) accA[nt][e] = 0.0f;
    if (NTILE == 2) {
#pragma unroll
        for (int nt = 0; nt < 8; nt++)
#pragma unroll
            for (int e = 0; e < 4; e++) accB[nt][e] = 0.0f;
    }
    {
        int kEnd = (NTILE == 2) ? mtb : mta;
        for (int ks = ks0; ks <= kEnd; ks++) {
            int off = ks * 8 + c * 2;
            uint2 vb[8];
#pragma unroll
            for (int nt = 0; nt < 8; nt++) {
                int hr = c0 + nt * 8 + g;
                vb[nt] = *(const uint2*)(HT + hr * PWA + (off ^ swz(hr)));
            }
            if (NTILE == 2) {
                uint4 bv = L2f[(mtb * 8 + ks) * 32 + lane];
#pragma unroll
                for (int nt = 0; nt < 8; nt++)
                    mma16816(accB[nt], bv.x, bv.y, bv.z, bv.w, vb[nt].x, vb[nt].y);
            }
            if (ks <= mta) {
                uint4 av = L2f[(mta * 8 + ks) * 32 + lane];
#pragma unroll
                for (int nt = 0; nt < 8; nt++)
                    mma16816(accA[nt], av.x, av.y, av.z, av.w, vb[nt].x, vb[nt].y);
            }
        }
    }
#pragma unroll
    for (int ti = 0; ti < NTILE; ti++)
#pragma unroll
        for (int nt = 0; nt < 8; nt++)
#pragma unroll
            for (int e = 0; e < 4; e++) {
                int f = c0 + nt * 8 + (c << 1) + (e & 1);
                fcT[ti * 2 + (e >> 1)] +=
                    (ti ? accB[nt][e] : accA[nt][e]) * s_fcw[f];
            }

    // ---------------- fc reduce -> g_h ----------------
#pragma unroll
    for (int i = 0; i < 2 * NTILE; i++) {
        fcT[i] += __shfl_xor_sync(0xffffffffu, fcT[i], 1);
        fcT[i] += __shfl_xor_sync(0xffffffffu, fcT[i], 2);
    }
    if (c == 0) {
#pragma unroll
        for (int i = 0; i < 2 * NTILE; i++) {
            int t = ((i >> 1) ? mtb : mta) * 16 + g + 8 * (i & 1);
            scrF[wg * 128 + t] = fcT[i];
        }
    }
    __syncthreads();
    if (tid < MT * 16) {
        int t = tid;
        float d = scrF[t] + scrF[128 + t];
        g_h[(n0 + sbase + t / TK) * 224 + hoff + (t & (TK - 1))] = d + fcb;
    }
    __syncthreads();
}

__global__ void __launch_bounds__(NTH, 2) kA17(
    const float* __restrict__ x,
    const float* __restrict__ cb0, const float* __restrict__ lg0,
    const float* __restrict__ lb0,
    const float* __restrict__ cb1, const float* __restrict__ lg1,
    const float* __restrict__ lb1,
    const float* __restrict__ cb2, const float* __restrict__ lg2,
    const float* __restrict__ lb2,
    const float* __restrict__ fcw, const float* __restrict__ fcbp) {
    extern __shared__ uint32_t smw[];
    uint32_t* X = smw + X_OFF;
    float* scr = (float*)(smw + SCR_BASE);
    const int tid = threadIdx.x;
    if (tid < 128) scr[32 + tid] = fcw[tid];
    float fcb = fcbp[0];
    int n0 = blockIdx.x * 2;

    // ---- build X once ----
#pragma unroll 4
    for (int it = 0; it < 32; it++) {
        int idx = it * 256 + tid;
        int r = idx >> 5, f4 = idx & 31;
        const float4 v = ((const float4*)(x +
            ((size_t)(n0 + (r >> 7)) * 128 + (r & 127)) * 128))[f4];
        __half2 h0, h1;
        h0.x = __float2half(v.x); h0.y = __float2half(v.y);
        h1.x = __float2half(v.z); h1.y = __float2half(v.w);
        int k2 = f4 << 2;
        int sw = swz(r);
        X[r * PWA + (wslotA(k2) ^ sw)]     = *(uint32_t*)&h0;
        X[r * PWA + (wslotA(k2 + 2) ^ sw)] = *(uint32_t*)&h1;
    }
    __syncthreads();

    run_scale<128, 8>(n0, 0, 0, lg0, lb0, g_Lf[0], g_Lf[1], 0, cb0, fcb, true);
    run_scale<128, 8>(n0, 1, 0, lg0, lb0, g_Lf[0], g_Lf[1], 0, cb0, fcb, false);
    run_scale<64, 8>(n0, 0, 1, lg1, lb1, g_Lf[2], g_Lf[3], 128, cb1, fcb, true);
    run_scale<32, 4>(n0, 0, 3, lg2, lb2, g_Lf[4], g_Lf[5], 192, cb2, fcb, true);

    // ---- fused kB1: block-local LN partials ----
    float s = 0.0f, s2 = 0.0f;
    for (int i = tid; i < 448; i += 256) {
        float v = g_h[n0 * 224 + i];
        s += v; s2 += v * v;
    }
#pragma unroll
    for (int o = 16; o; o >>= 1) {
        s  += __shfl_down_sync(0xffffffffu, s, o);
        s2 += __shfl_down_sync(0xffffffffu, s2, o);
    }
    float* scrR = scr + 288;
    int wI = tid >> 5, lI = tid & 31;
    if (lI == 0) { scrR[wI] = s; scrR[8 + wI] = s2; }
    __syncthreads();
    if (tid == 0) {
        float a = 0.0f, b = 0.0f;
#pragma unroll
        for (int i = 0; i < 8; i++) { a += scrR[i]; b += scrR[8 + i]; }
        g_bpart[blockIdx.x] = a;
        g_bpart[2048 + blockIdx.x] = b;
    }
}

// ============================================================================
// phase 2
// ============================================================================
__device__ __forceinline__ void bredsum(float& v, float* scr, int nthr) {
#pragma unroll
    for (int o = 16; o > 0; o >>= 1)
        v += __shfl_down_sync(0xffffffffu, v, o);
    int w = threadIdx.x >> 5, l = threadIdx.x & 31;
    if (l == 0) scr[w] = v;
    __syncthreads();
    if (threadIdx.x == 0) {
        float a = 0.f;
        int nw = (nthr + 31) >> 5;
        for (int i = 0; i < nw; i++) a += scr[i];
        scr[0] = a;
    }
    __syncthreads();
    v = scr[0];
}

// kC1: grid=64, block=896. Partials written [m][b][j] for streaming kC2.
__global__ void __launch_bounds__(896, 1) kC1(
    const float* __restrict__ M1,
    const float* __restrict__ slg,
    const float* __restrict__ slb) {
    __shared__ float sM1[64 * 64];
    __shared__ float scr[32];
    const int tid = threadIdx.x;
    const int j = tid % 224;
    const int mq = tid / 224;           // 0..3
    const int b = blockIdx.x;           // 0..63
    const int n0 = b * 64;

    float s = 0.0f, s2 = 0.0f;
    for (int i = tid; i < 2048; i += 896) {
        s  += g_bpart[i];
        s2 += g_bpart[2048 + i];
    }
    bredsum(s, scr, 896);
    __syncthreads();
    bredsum(s2, scr, 896);
    const float inv = 1.0f / (4096.0f * 224.0f);
    float mu = s * inv;
    float var = s2 * inv - mu * mu;
    float rinv = rsqrtf(var + 1e-5f);

    for (int i = tid; i < 4096; i += 896) {
        int m = i >> 6, nn = i & 63;
        sM1[i] = M1[m * 4096 + n0 + nn];
    }
    __syncthreads();

    float acc[16];
#pragma unroll
    for (int mi = 0; mi < 16; mi++) acc[mi] = 0.0f;
    const float* sM1q = sM1 + mq * 16 * 64;
#pragma unroll 4
    for (int nn = 0; nn < 64; nn++) {
        int off = (n0 + nn) * 224 + j;
        float hn = (g_h[off] - mu) * rinv * slg[off] + slb[off];
#pragma unroll
        for (int mi = 0; mi < 16; mi++)
            acc[mi] += sM1q[mi * 64 + nn] * hn;
    }
#pragma unroll
    for (int mi = 0; mi < 16; mi++)
        g_cpart[((mq * 16 + mi) * 64 + b) * 224 + j] = acc[mi];
}

// kC2: per block m, stream the contiguous 64x224 partial region.
__global__ void kC2(const float* __restrict__ smw_) {
    int m = blockIdx.x, j = threadIdx.x;
    const float* base = g_cpart + m * 64 * 224 + j;
    float g = 0.f;
    for (int b = 0; b < 64; b++) g += base[b * 224];
    float v = hswf(g) * smw_[224 + j];
    __shared__ float scr[32];
    bredsum(v, scr, 224);
    if (threadIdx.x == 0) g_gw[m] = v;
}

__global__ void kD(const float* __restrict__ M2,
                   const float* __restrict__ smw_,
                   const float* __restrict__ smb,
                   float* __restrict__ out) {
    int warp = threadIdx.x >> 5, lane = threadIdx.x & 31;
    int n = blockIdx.x * 8 + warp;
    float acc = 0.f;
#pragma unroll
    for (int i = 0; i < 7; i++) {
        int j = lane + 32 * i;
        acc += g_h[n * 224 + j] * (smw_[j] + smw_[224 + j]);
    }
#pragma unroll
    for (int i = 0; i < 2; i++) {
        int m = lane + 32 * i;
        acc += M2[n * 64 + m] * g_gw[m];
    }
#pragma unroll
    for (int o = 16; o > 0; o >>= 1)
        acc += __shfl_down_sync(0xffffffffu, acc, o);
    if (lane == 0) out[n] = acc + smb[0];
}

// ============================================================================
extern "C" void kernel_launch(void* const* d_in, const int* in_sizes, int n_in,
                              void* d_out, int out_size) {
    const float* x   = (const float*)d_in[0];
    const float* cw0 = (const float*)d_in[1];
    const float* cb0 = (const float*)d_in[2];
    const float* lg0 = (const float*)d_in[3];
    const float* lb0 = (const float*)d_in[4];
    const float* L10 = (const float*)d_in[5];
    const float* L20 = (const float*)d_in[6];
    const float* cw1 = (const float*)d_in[7];
    const float* cb1 = (const float*)d_in[8];
    const float* lg1 = (const float*)d_in[9];
    const float* lb1 = (const float*)d_in[10];
    const float* L11 = (const float*)d_in[11];
    const float* L21 = (const float*)d_in[12];
    const float* cw2 = (const float*)d_in[13];
    const float* cb2 = (const float*)d_in[14];
    const float* lg2 = (const float*)d_in[15];
    const float* lb2 = (const float*)d_in[16];
    const float* L12 = (const float*)d_in[17];
    const float* L22 = (const float*)d_in[18];
    const float* fcw = (const float*)d_in[19];
    const float* fcb = (const float*)d_in[20];
    const float* slg = (const float*)d_in[21];
    const float* slb = (const float*)d_in[22];
    const float* M1  = (const float*)d_in[23];
    const float* M2  = (const float*)d_in[24];
    const float* smw = (const float*)d_in[25];
    const float* smb = (const float*)d_in[26];
    float* out = (float*)d_out;

    cudaFuncSetAttribute(kA17, cudaFuncAttributeMaxDynamicSharedMemorySize,
                         SMEM_SZ);

    kW<<<13, 256>>>(cw0, cw1, cw2, L10, L20, L11, L21, L12, L22);
    kA17<<<2048, NTH, SMEM_SZ>>>(x, cb0, lg0, lb0, cb1, lg1, lb1,
                                 cb2, lg2, lb2, fcw, fcb);
    kC1<<<64, 896>>>(M1, slg, slb);
    kC2<<<64, 224>>>(smw);
    kD<<<512, 256>>>(M2, smw, smb, out);
}